// round 7
// baseline (speedup 1.0000x reference)
#include <cstdint>
#include <cuda_runtime.h>
#include <cuda_bf16.h>
#include <mma.h>
#include <math.h>

using namespace nvcuda;

#define DD  256
#define NBA 1024
#define TT  128

// strides (elements)
#define LDXB 264     // X tile bf16 [128 x 256]
#define LDW1 72      // Wfc tile bf16 [256 x 64]
#define LDW2 264     // Wpr tile bf16 [64 x 256]
#define LDHF 68      // Hf tile f32  [128 x 64]
#define LDHB 72      // Hb tile bf16 [128 x 64]

// smem layout (bytes)
#define SM_X    0
#define SM_WFC  67584                 // + 128*264*2
#define SM_WPR  104448                // + 256*72*2
#define SM_HF0  138240                // + 64*264*2
#define SM_HF1  173056                // + 128*68*4
#define SM_HB   207872                // + 128*68*4
#define SMEM_TOTAL 226304             // + 128*72*2

__device__ __nv_bfloat16 g_wfcb[256 * 1024];   // row-major [k=256, n=1024]
__device__ __nv_bfloat16 g_wprb[1024 * 256];   // row-major [k=1024, n=256]
__device__ float g_yo[NBA * DD];

// ---------------------------------------------------------------------------
__device__ __forceinline__ void cp16(void* sdst, const void* gsrc) {
    unsigned s = (unsigned)__cvta_generic_to_shared(sdst);
    asm volatile("cp.async.cg.shared.global [%0], [%1], 16;" :: "r"(s), "l"(gsrc));
}
#define CP_COMMIT() asm volatile("cp.async.commit_group;" ::: "memory")
#define CP_WAIT0()  asm volatile("cp.async.wait_group 0;" ::: "memory")

// ---------------------------------------------------------------------------
// fp32 -> bf16 weight copies (once per launch, deterministic)
// ---------------------------------------------------------------------------
__global__ void convert_kernel(const float* __restrict__ wfc, const float* __restrict__ wpr) {
    int i = blockIdx.x * blockDim.x + threadIdx.x;   // 0..65535
    float4 a = ((const float4*)wfc)[i];
    ((__nv_bfloat162*)g_wfcb)[i * 2]     = __floats2bfloat162_rn(a.x, a.y);
    ((__nv_bfloat162*)g_wfcb)[i * 2 + 1] = __floats2bfloat162_rn(a.z, a.w);
    float4 b = ((const float4*)wpr)[i];
    ((__nv_bfloat162*)g_wprb)[i * 2]     = __floats2bfloat162_rn(b.x, b.y);
    ((__nv_bfloat162*)g_wprb)[i * 2 + 1] = __floats2bfloat162_rn(b.z, b.w);
}

// ---------------------------------------------------------------------------
// yo[b,a,:] = ((cx @ wkv)[:, D:2D] + bkv[D:2D]) @ wo + bo
// ---------------------------------------------------------------------------
__global__ void yo_kernel(const float* __restrict__ cx, const float* __restrict__ wkv,
                          const float* __restrict__ bkv, const float* __restrict__ wo,
                          const float* __restrict__ bo) {
    __shared__ float sCX[4][DD];
    __shared__ float sV[4][DD];
    int tid = threadIdx.x;
    int r0 = blockIdx.x * 4;
    #pragma unroll
    for (int i = 0; i < 4; i++) sCX[i][tid] = cx[(r0 + i) * DD + tid];
    __syncthreads();
    float acc[4];
    #pragma unroll
    for (int i = 0; i < 4; i++) acc[i] = bkv[DD + tid];
    for (int c = 0; c < DD; c++) {
        float w = wkv[c * 512 + DD + tid];
        #pragma unroll
        for (int i = 0; i < 4; i++) acc[i] += sCX[i][c] * w;
    }
    #pragma unroll
    for (int i = 0; i < 4; i++) sV[i][tid] = acc[i];
    __syncthreads();
    float a2[4];
    #pragma unroll
    for (int i = 0; i < 4; i++) a2[i] = bo[tid];
    for (int k = 0; k < DD; k++) {
        float w = wo[k * DD + tid];
        #pragma unroll
        for (int i = 0; i < 4; i++) a2[i] += sV[i][k] * w;
    }
    #pragma unroll
    for (int i = 0; i < 4; i++) g_yo[(r0 + i) * DD + tid] = a2[i];
}

// ---------------------------------------------------------------------------
// Fused LN1 -> +yo -> LN2 -> warp-specialized pipelined MLP -> +x3
// One block per (b,a): 128 rows, 512 threads / 16 warps.
//  warps 0-7  (T): GEMM1(jt) while warps 8-15 (G): gelu(jt-1) + Wpr staging
//  all 16 warps:   GEMM2(jt-1)
// ---------------------------------------------------------------------------
__global__ void __launch_bounds__(512, 1)
mlp_kernel(const float* __restrict__ x,
           const float* __restrict__ ln1w, const float* __restrict__ ln1b,
           const float* __restrict__ ln2w, const float* __restrict__ ln2b,
           const float* __restrict__ bfc,  const float* __restrict__ bpr,
           float* __restrict__ out) {
    extern __shared__ char smem[];
    __nv_bfloat16* sXb  = (__nv_bfloat16*)(smem + SM_X);
    __nv_bfloat16* sWfc = (__nv_bfloat16*)(smem + SM_WFC);
    __nv_bfloat16* sWpr = (__nv_bfloat16*)(smem + SM_WPR);
    __nv_bfloat16* sHb  = (__nv_bfloat16*)(smem + SM_HB);

    int tid  = threadIdx.x;
    int warp = tid >> 5;
    int lane = tid & 31;
    bool isT = warp < 8;
    int ba = blockIdx.x;
    size_t row0 = (size_t)ba * TT;

    // prefetch Wfc tile jt=0 (overlaps LN)
    #pragma unroll
    for (int t = 0; t < 4; t++) {
        int idx = tid + t * 512, r = idx >> 3, c8 = idx & 7;
        cp16((char*)sWfc + r * 144 + c8 * 16, g_wfcb + (size_t)r * 1024 + c8 * 8);
    }
    CP_COMMIT();

    // -------- LN phase (8 rows per warp): fp32 x3 -> out, bf16 X -> sXb
    {
        float lw1[8], lb1[8], lw2[8], lb2[8], yo[8];
        float4 a, b;
        a = ((const float4*)ln1w)[lane*2]; b = ((const float4*)ln1w)[lane*2+1];
        lw1[0]=a.x;lw1[1]=a.y;lw1[2]=a.z;lw1[3]=a.w;lw1[4]=b.x;lw1[5]=b.y;lw1[6]=b.z;lw1[7]=b.w;
        a = ((const float4*)ln1b)[lane*2]; b = ((const float4*)ln1b)[lane*2+1];
        lb1[0]=a.x;lb1[1]=a.y;lb1[2]=a.z;lb1[3]=a.w;lb1[4]=b.x;lb1[5]=b.y;lb1[6]=b.z;lb1[7]=b.w;
        a = ((const float4*)ln2w)[lane*2]; b = ((const float4*)ln2w)[lane*2+1];
        lw2[0]=a.x;lw2[1]=a.y;lw2[2]=a.z;lw2[3]=a.w;lw2[4]=b.x;lw2[5]=b.y;lw2[6]=b.z;lw2[7]=b.w;
        a = ((const float4*)ln2b)[lane*2]; b = ((const float4*)ln2b)[lane*2+1];
        lb2[0]=a.x;lb2[1]=a.y;lb2[2]=a.z;lb2[3]=a.w;lb2[4]=b.x;lb2[5]=b.y;lb2[6]=b.z;lb2[7]=b.w;
        const float* yor = g_yo + (size_t)ba * DD;
        a = ((const float4*)yor)[lane*2]; b = ((const float4*)yor)[lane*2+1];
        yo[0]=a.x;yo[1]=a.y;yo[2]=a.z;yo[3]=a.w;yo[4]=b.x;yo[5]=b.y;yo[6]=b.z;yo[7]=b.w;

        for (int rr = 0; rr < 8; rr++) {
            int row = warp * 8 + rr;
            const float4* xr = (const float4*)(x + (row0 + row) * DD);
            float v[8];
            { float4 u0 = xr[lane*2], u1 = xr[lane*2+1];
              v[0]=u0.x;v[1]=u0.y;v[2]=u0.z;v[3]=u0.w;v[4]=u1.x;v[5]=u1.y;v[6]=u1.z;v[7]=u1.w; }
            float s = 0.f, q = 0.f;
            #pragma unroll
            for (int j = 0; j < 8; j++) { s += v[j]; q += v[j]*v[j]; }
            #pragma unroll
            for (int o = 16; o > 0; o >>= 1) { s += __shfl_xor_sync(~0u,s,o); q += __shfl_xor_sync(~0u,q,o); }
            float mu = s * (1.f/DD);
            float rs = rsqrtf(q * (1.f/DD) - mu*mu + 1e-5f);
            float tv[8]; s = 0.f; q = 0.f;
            #pragma unroll
            for (int j = 0; j < 8; j++) {
                tv[j] = (v[j]-mu)*rs*lw1[j] + lb1[j] + yo[j];
                s += tv[j]; q += tv[j]*tv[j];
            }
            #pragma unroll
            for (int o = 16; o > 0; o >>= 1) { s += __shfl_xor_sync(~0u,s,o); q += __shfl_xor_sync(~0u,q,o); }
            float mu2 = s * (1.f/DD);
            float rs2 = rsqrtf(q * (1.f/DD) - mu2*mu2 + 1e-5f);
            #pragma unroll
            for (int j = 0; j < 8; j++) v[j] = (tv[j]-mu2)*rs2*lw2[j] + lb2[j];

            float* orow = out + (row0 + row) * DD;
            ((float4*)orow)[lane*2]   = make_float4(v[0],v[1],v[2],v[3]);
            ((float4*)orow)[lane*2+1] = make_float4(v[4],v[5],v[6],v[7]);

            __nv_bfloat162 p0 = __floats2bfloat162_rn(v[0],v[1]);
            __nv_bfloat162 p1 = __floats2bfloat162_rn(v[2],v[3]);
            __nv_bfloat162 p2 = __floats2bfloat162_rn(v[4],v[5]);
            __nv_bfloat162 p3 = __floats2bfloat162_rn(v[6],v[7]);
            uint4 pk;
            pk.x = *(unsigned*)&p0; pk.y = *(unsigned*)&p1; pk.z = *(unsigned*)&p2; pk.w = *(unsigned*)&p3;
            *(uint4*)(sXb + row * LDXB + lane * 8) = pk;
        }
    }
    CP_WAIT0();
    __syncthreads();

    // -------- pipelined mainloop
    wmma::fragment<wmma::accumulator, 16, 16, 16, float> acc2[2][4];
    #pragma unroll
    for (int m = 0; m < 2; m++)
        #pragma unroll
        for (int n = 0; n < 4; n++) wmma::fill_fragment(acc2[m][n], 0.f);

    int wm = (warp & 7) >> 1, wn = warp & 1;     // GEMM1 tiling (T warps)
    int wm2 = warp >> 2, wn2 = warp & 3;         // GEMM2 tiling (all warps)
    int g = tid - 256;                           // G-thread index
    uint4 wreg[8];                               // Wpr staging (G warps)

    for (int jt = 0; jt <= 16; jt++) {
        // ================= phase A =================
        if (isT) {
            if (jt < 16) {
                float* Hf = (float*)(smem + ((jt & 1) ? SM_HF1 : SM_HF0));
                wmma::fragment<wmma::accumulator, 16, 16, 16, float> c00, c01, c10, c11;
                wmma::fill_fragment(c00, 0.f); wmma::fill_fragment(c01, 0.f);
                wmma::fill_fragment(c10, 0.f); wmma::fill_fragment(c11, 0.f);
                const __nv_bfloat16* Xb = sXb + (wm * 32) * LDXB;
                #pragma unroll
                for (int k = 0; k < 256; k += 16) {
                    wmma::fragment<wmma::matrix_a, 16, 16, 16, __nv_bfloat16, wmma::row_major> a0, a1;
                    wmma::fragment<wmma::matrix_b, 16, 16, 16, __nv_bfloat16, wmma::row_major> b0, b1;
                    wmma::load_matrix_sync(a0, Xb + k, LDXB);
                    wmma::load_matrix_sync(a1, Xb + 16 * LDXB + k, LDXB);
                    wmma::load_matrix_sync(b0, sWfc + k * LDW1 + wn * 32, LDW1);
                    wmma::load_matrix_sync(b1, sWfc + k * LDW1 + wn * 32 + 16, LDW1);
                    wmma::mma_sync(c00, a0, b0, c00);
                    wmma::mma_sync(c01, a0, b1, c01);
                    wmma::mma_sync(c10, a1, b0, c10);
                    wmma::mma_sync(c11, a1, b1, c11);
                }
                wmma::store_matrix_sync(Hf + (wm*32)*LDHF + wn*32,          c00, LDHF, wmma::mem_row_major);
                wmma::store_matrix_sync(Hf + (wm*32)*LDHF + wn*32 + 16,     c01, LDHF, wmma::mem_row_major);
                wmma::store_matrix_sync(Hf + (wm*32+16)*LDHF + wn*32,       c10, LDHF, wmma::mem_row_major);
                wmma::store_matrix_sync(Hf + (wm*32+16)*LDHF + wn*32 + 16,  c11, LDHF, wmma::mem_row_major);
            }
        } else {
            int r = g >> 2, q = g & 3;
            if (jt >= 1) {
                // store Wpr(jt-1) regs -> smem
                uint4* dst = (uint4*)((char*)sWpr + r * 528 + q * 128);
                #pragma unroll
                for (int j = 0; j < 8; j++) dst[j] = wreg[j];
                // gelu(jt-1): Hf[(jt-1)&1] -> Hb (bf16)
                const float* Hf = (const float*)(smem + (((jt-1) & 1) ? SM_HF1 : SM_HF0));
                const float* bf = bfc + (jt - 1) * 64;
                #pragma unroll
                for (int t = 0; t < 32; t++) {
                    int e = g + t * 256, rr = e >> 6, c = e & 63;
                    float v = Hf[rr * LDHF + c] + bf[c];
                    v = 0.5f * v * (1.f + erff(v * 0.70710678118654752f));
                    sHb[rr * LDHB + c] = __float2bfloat16_rn(v);
                }
            }
            if (jt < 16) {
                // LDG Wpr(jt) -> regs (consumed at A(jt+1))
                const uint4* src = (const uint4*)((const char*)g_wprb +
                                   ((size_t)(jt * 64 + r) * 256 + q * 64) * 2);
                #pragma unroll
                for (int j = 0; j < 8; j++) wreg[j] = src[j];
            }
        }
        __syncthreads();

        // ================= phase B =================
        if (jt + 1 < 16) {   // prefetch Wfc(jt+1) under GEMM2
            #pragma unroll
            for (int t = 0; t < 4; t++) {
                int idx = tid + t * 512, r = idx >> 3, c8 = idx & 7;
                cp16((char*)sWfc + r * 144 + c8 * 16,
                     g_wfcb + (size_t)r * 1024 + (jt + 1) * 64 + c8 * 8);
            }
            CP_COMMIT();
        }
        if (jt >= 1) {
            #pragma unroll
            for (int k2 = 0; k2 < 64; k2 += 16) {
                wmma::fragment<wmma::matrix_a, 16, 16, 16, __nv_bfloat16, wmma::row_major> a0, a1;
                wmma::load_matrix_sync(a0, sHb + (wm2 * 32) * LDHB + k2, LDHB);
                wmma::load_matrix_sync(a1, sHb + (wm2 * 32 + 16) * LDHB + k2, LDHB);
                #pragma unroll
                for (int n = 0; n < 4; n++) {
                    wmma::fragment<wmma::matrix_b, 16, 16, 16, __nv_bfloat16, wmma::row_major> b;
                    wmma::load_matrix_sync(b, sWpr + k2 * LDW2 + wn2 * 64 + n * 16, LDW2);
                    wmma::mma_sync(acc2[0][n], a0, b, acc2[0][n]);
                    wmma::mma_sync(acc2[1][n], a1, b, acc2[1][n]);
                }
            }
        }
        CP_WAIT0();
        __syncthreads();
    }

    // -------- epilogue: out = x3 + mlp + b_pr (4 column passes via HF0 staging)
    float* S = (float*)(smem + SM_HF0);
    for (int n = 0; n < 4; n++) {
        __syncthreads();
        wmma::store_matrix_sync(S + (wm2 * 32) * LDHF + wn2 * 16,      acc2[0][n], LDHF, wmma::mem_row_major);
        wmma::store_matrix_sync(S + (wm2 * 32 + 16) * LDHF + wn2 * 16, acc2[1][n], LDHF, wmma::mem_row_major);
        __syncthreads();
        #pragma unroll
        for (int t = 0; t < 16; t++) {
            int e = tid + t * 512, r = e >> 6, lc = e & 63;
            int strip = lc >> 4, w = lc & 15;
            int gcol = strip * 64 + n * 16 + w;
            size_t gi = (row0 + r) * DD + gcol;
            out[gi] = out[gi] + S[r * LDHF + lc] + bpr[gcol];
        }
    }
}

// ---------------------------------------------------------------------------
extern "C" void kernel_launch(void* const* d_in, const int* in_sizes, int n_in,
                              void* d_out, int out_size) {
    const float* x    = (const float*)d_in[0];
    const float* cx   = (const float*)d_in[1];
    const float* ln1w = (const float*)d_in[2];
    const float* ln1b = (const float*)d_in[3];
    // d_in[4]=wq, d_in[5]=bq: unused (uniform softmax over equal logits; V constant over keys)
    const float* wkv  = (const float*)d_in[6];
    const float* bkv  = (const float*)d_in[7];
    const float* wo   = (const float*)d_in[8];
    const float* bo   = (const float*)d_in[9];
    const float* ln2w = (const float*)d_in[10];
    const float* ln2b = (const float*)d_in[11];
    const float* wfc  = (const float*)d_in[12];
    const float* bfc  = (const float*)d_in[13];
    const float* wpr  = (const float*)d_in[14];
    const float* bpr  = (const float*)d_in[15];
    float* out = (float*)d_out;

    cudaFuncSetAttribute(mlp_kernel, cudaFuncAttributeMaxDynamicSharedMemorySize, SMEM_TOTAL);

    convert_kernel<<<256, 256>>>(wfc, wpr);
    yo_kernel<<<256, 256>>>(cx, wkv, bkv, wo, bo);
    mlp_kernel<<<NBA, 512, SMEM_TOTAL>>>(x, ln1w, ln1b, ln2w, ln2b, bfc, bpr, out);
}

// round 8
// speedup vs baseline: 1.0550x; 1.0550x over previous
#include <cstdint>
#include <cuda_runtime.h>
#include <cuda_bf16.h>
#include <mma.h>
#include <math.h>

using namespace nvcuda;

#define DD  256
#define TT  128

// strides (elements)
#define LDXB  264   // X tile bf16 [64 x 256]
#define LDWFC 136   // Wfc pair tile bf16 [256 x 128]
#define LDWPR 264   // Wpr pair tile bf16 [128 x 256]
#define LDHF  132   // Hf tile f32 [64 x 128]
#define LDHB  136   // Hb tile bf16 [64 x 128]
#define LDSE  260   // epilogue stage f32 [64 x 256]

// smem layout (bytes)
#define SM_X    0                 // 64*264*2  = 33792
#define SM_WFC  33792             // 256*136*2 = 69632
#define SM_WPR  103424            // 128*264*2 = 67584
#define SM_HF   171008            // 64*132*4  = 33792
#define SM_HB   204800            // 64*136*2  = 17408
#define SMEM_TOTAL 222208

__device__ __nv_bfloat16 g_wfcb[256 * 1024];   // row-major [k=256, n=1024]
__device__ __nv_bfloat16 g_wprb[1024 * 256];   // row-major [k=1024, n=256]
__device__ float g_yo[1024 * DD];

// ---------------------------------------------------------------------------
__device__ __forceinline__ void cp16(void* sdst, const void* gsrc) {
    unsigned s = (unsigned)__cvta_generic_to_shared(sdst);
    asm volatile("cp.async.cg.shared.global [%0], [%1], 16;" :: "r"(s), "l"(gsrc));
}
#define CP_COMMIT() asm volatile("cp.async.commit_group;" ::: "memory")
#define CP_WAIT1()  asm volatile("cp.async.wait_group 1;" ::: "memory")
#define BAR_SYNC_1()   asm volatile("bar.sync 1, 512;" ::: "memory")
#define BAR_ARRIVE_1() asm volatile("bar.arrive 1, 512;" ::: "memory")

// ---------------------------------------------------------------------------
// prep: blocks 0-255 convert weights fp32->bf16; blocks 256-511 compute yo.
// yo[b,a,:] = ((cx @ wkv)[:, D:2D] + bkv[D:2D]) @ wo + bo
// ---------------------------------------------------------------------------
__global__ void prep_kernel(const float* __restrict__ wfc, const float* __restrict__ wpr,
                            const float* __restrict__ cx,  const float* __restrict__ wkv,
                            const float* __restrict__ bkv, const float* __restrict__ wo,
                            const float* __restrict__ bo) {
    __shared__ float sCX[4][DD];
    __shared__ float sV[4][DD];
    int tid = threadIdx.x;
    if (blockIdx.x < 256) {
        int i = blockIdx.x * 256 + tid;          // 0..65535
        float4 a = ((const float4*)wfc)[i];
        ((__nv_bfloat162*)g_wfcb)[i * 2]     = __floats2bfloat162_rn(a.x, a.y);
        ((__nv_bfloat162*)g_wfcb)[i * 2 + 1] = __floats2bfloat162_rn(a.z, a.w);
        float4 b = ((const float4*)wpr)[i];
        ((__nv_bfloat162*)g_wprb)[i * 2]     = __floats2bfloat162_rn(b.x, b.y);
        ((__nv_bfloat162*)g_wprb)[i * 2 + 1] = __floats2bfloat162_rn(b.z, b.w);
        return;
    }
    int r0 = (blockIdx.x - 256) * 4;
    #pragma unroll
    for (int i = 0; i < 4; i++) sCX[i][tid] = cx[(r0 + i) * DD + tid];
    __syncthreads();
    float acc[4];
    #pragma unroll
    for (int i = 0; i < 4; i++) acc[i] = bkv[DD + tid];
    for (int c = 0; c < DD; c++) {
        float w = wkv[c * 512 + DD + tid];
        #pragma unroll
        for (int i = 0; i < 4; i++) acc[i] += sCX[i][c] * w;
    }
    #pragma unroll
    for (int i = 0; i < 4; i++) sV[i][tid] = acc[i];
    __syncthreads();
    float a2[4];
    #pragma unroll
    for (int i = 0; i < 4; i++) a2[i] = bo[tid];
    for (int k = 0; k < DD; k++) {
        float w = wo[k * DD + tid];
        #pragma unroll
        for (int i = 0; i < 4; i++) a2[i] += sV[i][k] * w;
    }
    #pragma unroll
    for (int i = 0; i < 4; i++) g_yo[(r0 + i) * DD + tid] = a2[i];
}

// ---------------------------------------------------------------------------
// Fused LN1 -> +yo -> LN2 -> pipelined MLP -> +x3.  64 rows/block, grid 2048.
// Pair loop p: warps 0-7 GEMM1(p) while warps 8-15 gelu(p-1); all GEMM2(p-1).
// ---------------------------------------------------------------------------
__global__ void __launch_bounds__(512, 1)
mlp_kernel(const float* __restrict__ x,
           const float* __restrict__ ln1w, const float* __restrict__ ln1b,
           const float* __restrict__ ln2w, const float* __restrict__ ln2b,
           const float* __restrict__ bfc,  const float* __restrict__ bpr,
           float* __restrict__ out) {
    extern __shared__ char smem[];
    __nv_bfloat16* sXb  = (__nv_bfloat16*)(smem + SM_X);
    __nv_bfloat16* sWfc = (__nv_bfloat16*)(smem + SM_WFC);
    __nv_bfloat16* sWpr = (__nv_bfloat16*)(smem + SM_WPR);
    float*         sHf  = (float*)        (smem + SM_HF);
    __nv_bfloat16* sHb  = (__nv_bfloat16*)(smem + SM_HB);

    int tid  = threadIdx.x;
    int warp = tid >> 5;
    int lane = tid & 31;
    size_t row0 = (size_t)blockIdx.x * 64;

    // prefetch Wfc(0) (overlaps LN)
    #pragma unroll
    for (int t = 0; t < 8; t++) {
        int idx = tid + t * 512, r = idx >> 4, c8 = idx & 15;
        cp16((char*)sWfc + (r * LDWFC + c8 * 8) * 2, g_wfcb + (size_t)r * 1024 + c8 * 8);
    }
    CP_COMMIT();

    // -------- LN phase: 4 rows per warp; fp32 x3 -> out, bf16 X -> sXb
    {
        float lw1[8], lb1[8], lw2[8], lb2[8], yo[8];
        float4 a, b;
        a = ((const float4*)ln1w)[lane*2]; b = ((const float4*)ln1w)[lane*2+1];
        lw1[0]=a.x;lw1[1]=a.y;lw1[2]=a.z;lw1[3]=a.w;lw1[4]=b.x;lw1[5]=b.y;lw1[6]=b.z;lw1[7]=b.w;
        a = ((const float4*)ln1b)[lane*2]; b = ((const float4*)ln1b)[lane*2+1];
        lb1[0]=a.x;lb1[1]=a.y;lb1[2]=a.z;lb1[3]=a.w;lb1[4]=b.x;lb1[5]=b.y;lb1[6]=b.z;lb1[7]=b.w;
        a = ((const float4*)ln2w)[lane*2]; b = ((const float4*)ln2w)[lane*2+1];
        lw2[0]=a.x;lw2[1]=a.y;lw2[2]=a.z;lw2[3]=a.w;lw2[4]=b.x;lw2[5]=b.y;lw2[6]=b.z;lw2[7]=b.w;
        a = ((const float4*)ln2b)[lane*2]; b = ((const float4*)ln2b)[lane*2+1];
        lb2[0]=a.x;lb2[1]=a.y;lb2[2]=a.z;lb2[3]=a.w;lb2[4]=b.x;lb2[5]=b.y;lb2[6]=b.z;lb2[7]=b.w;
        const float* yor = g_yo + (row0 >> 7) * DD;   // (b,a) = global_row / 128
        a = ((const float4*)yor)[lane*2]; b = ((const float4*)yor)[lane*2+1];
        yo[0]=a.x;yo[1]=a.y;yo[2]=a.z;yo[3]=a.w;yo[4]=b.x;yo[5]=b.y;yo[6]=b.z;yo[7]=b.w;

        for (int rr = 0; rr < 4; rr++) {
            int row = warp * 4 + rr;
            const float4* xr = (const float4*)(x + (row0 + row) * DD);
            float v[8];
            { float4 u0 = xr[lane*2], u1 = xr[lane*2+1];
              v[0]=u0.x;v[1]=u0.y;v[2]=u0.z;v[3]=u0.w;v[4]=u1.x;v[5]=u1.y;v[6]=u1.z;v[7]=u1.w; }
            float s = 0.f, q = 0.f;
            #pragma unroll
            for (int j = 0; j < 8; j++) { s += v[j]; q += v[j]*v[j]; }
            #pragma unroll
            for (int o = 16; o > 0; o >>= 1) { s += __shfl_xor_sync(~0u,s,o); q += __shfl_xor_sync(~0u,q,o); }
            float mu = s * (1.f/DD);
            float rs = rsqrtf(q * (1.f/DD) - mu*mu + 1e-5f);
            float tv[8]; s = 0.f; q = 0.f;
            #pragma unroll
            for (int j = 0; j < 8; j++) {
                tv[j] = (v[j]-mu)*rs*lw1[j] + lb1[j] + yo[j];
                s += tv[j]; q += tv[j]*tv[j];
            }
            #pragma unroll
            for (int o = 16; o > 0; o >>= 1) { s += __shfl_xor_sync(~0u,s,o); q += __shfl_xor_sync(~0u,q,o); }
            float mu2 = s * (1.f/DD);
            float rs2 = rsqrtf(q * (1.f/DD) - mu2*mu2 + 1e-5f);
            #pragma unroll
            for (int j = 0; j < 8; j++) v[j] = (tv[j]-mu2)*rs2*lw2[j] + lb2[j];

            float* orow = out + (row0 + row) * DD;
            ((float4*)orow)[lane*2]   = make_float4(v[0],v[1],v[2],v[3]);
            ((float4*)orow)[lane*2+1] = make_float4(v[4],v[5],v[6],v[7]);

            __nv_bfloat162 p0 = __floats2bfloat162_rn(v[0],v[1]);
            __nv_bfloat162 p1 = __floats2bfloat162_rn(v[2],v[3]);
            __nv_bfloat162 p2 = __floats2bfloat162_rn(v[4],v[5]);
            __nv_bfloat162 p3 = __floats2bfloat162_rn(v[6],v[7]);
            uint4 pk;
            pk.x = *(unsigned*)&p0; pk.y = *(unsigned*)&p1; pk.z = *(unsigned*)&p2; pk.w = *(unsigned*)&p3;
            *(uint4*)(sXb + row * LDXB + lane * 8) = pk;
        }
    }

    // -------- pipelined mainloop over 8 jt-pairs (+1 drain iteration)
    wmma::fragment<wmma::accumulator, 16, 16, 16, float> acc2[2][2];
    #pragma unroll
    for (int m = 0; m < 2; m++)
        #pragma unroll
        for (int n = 0; n < 2; n++) wmma::fill_fragment(acc2[m][n], 0.f);

    int wm1 = warp & 1, wn1 = warp >> 1;       // GEMM1 (warps 0-7): rows wm1*32, cols wn1*32
    int wm2 = warp & 1, wn2 = warp >> 1;       // GEMM2 (all): rows wm2*32, cols wn2*32
    int g = tid - 256;                         // gelu-team thread index

    for (int p = 0; p <= 8; p++) {
        __syncthreads();                       // GEMM2(p-2) done -> sWpr free
        if (p >= 1) {                          // load Wpr(p-1)
            #pragma unroll
            for (int t = 0; t < 8; t++) {
                int idx = tid + t * 512, r = idx >> 5, c8 = idx & 31;
                cp16((char*)sWpr + (r * LDWPR + c8 * 8) * 2,
                     g_wprb + ((size_t)((p - 1) * 128 + r)) * 256 + c8 * 8);
            }
        }
        CP_COMMIT();
        CP_WAIT1();                            // own Wfc(p) chunks done
        __syncthreads();                       // all Wfc(p) visible

        // ---- phase A: GEMM1(p) [warps 0-7] || gelu(p-1) [warps 8-15]
        if (warp < 8) {
            wmma::fragment<wmma::accumulator, 16, 16, 16, float> c00, c01, c10, c11;
            if (p < 8) {
                wmma::fill_fragment(c00, 0.f); wmma::fill_fragment(c01, 0.f);
                wmma::fill_fragment(c10, 0.f); wmma::fill_fragment(c11, 0.f);
                const __nv_bfloat16* Xb = sXb + (wm1 * 32) * LDXB;
                #pragma unroll
                for (int k = 0; k < 256; k += 16) {
                    wmma::fragment<wmma::matrix_a, 16, 16, 16, __nv_bfloat16, wmma::row_major> a0, a1;
                    wmma::fragment<wmma::matrix_b, 16, 16, 16, __nv_bfloat16, wmma::row_major> b0, b1;
                    wmma::load_matrix_sync(a0, Xb + k, LDXB);
                    wmma::load_matrix_sync(a1, Xb + 16 * LDXB + k, LDXB);
                    wmma::load_matrix_sync(b0, sWfc + k * LDWFC + wn1 * 32, LDWFC);
                    wmma::load_matrix_sync(b1, sWfc + k * LDWFC + wn1 * 32 + 16, LDWFC);
                    wmma::mma_sync(c00, a0, b0, c00);
                    wmma::mma_sync(c01, a0, b1, c01);
                    wmma::mma_sync(c10, a1, b0, c10);
                    wmma::mma_sync(c11, a1, b1, c11);
                }
            }
            BAR_SYNC_1();                      // wait: gelu team done READING Hf(p-1)
            if (p < 8) {
                wmma::store_matrix_sync(sHf + (wm1*32)*LDHF + wn1*32,          c00, LDHF, wmma::mem_row_major);
                wmma::store_matrix_sync(sHf + (wm1*32)*LDHF + wn1*32 + 16,     c01, LDHF, wmma::mem_row_major);
                wmma::store_matrix_sync(sHf + (wm1*32+16)*LDHF + wn1*32,       c10, LDHF, wmma::mem_row_major);
                wmma::store_matrix_sync(sHf + (wm1*32+16)*LDHF + wn1*32 + 16,  c11, LDHF, wmma::mem_row_major);
            }
        } else {
            if (p >= 1) {
                const float* bf = bfc + (p - 1) * 128;
                #pragma unroll
                for (int t = 0; t < 32; t++) {
                    int e = g + t * 256, r = e >> 7, c = e & 127;
                    float v = sHf[r * LDHF + c] + bf[c];
                    v = 0.5f * v * (1.f + erff(v * 0.70710678118654752f));
                    sHb[r * LDHB + c] = __float2bfloat16_rn(v);
                }
            }
            BAR_ARRIVE_1();                    // signal: done reading Hf(p-1)
        }
        __syncthreads();                       // Hf(p), Hb(p-1) complete; Wfc readers done

        if (p < 7) {                           // load Wfc(p+1)
            #pragma unroll
            for (int t = 0; t < 8; t++) {
                int idx = tid + t * 512, r = idx >> 4, c8 = idx & 15;
                cp16((char*)sWfc + (r * LDWFC + c8 * 8) * 2,
                     g_wfcb + (size_t)r * 1024 + (p + 1) * 128 + c8 * 8);
            }
        }
        CP_COMMIT();
        CP_WAIT1();                            // own Wpr(p-1) chunks done
        __syncthreads();                       // all Wpr(p-1) visible

        // ---- phase B: GEMM2(p-1), all 16 warps
        if (p >= 1) {
            #pragma unroll
            for (int k2 = 0; k2 < 128; k2 += 16) {
                wmma::fragment<wmma::matrix_a, 16, 16, 16, __nv_bfloat16, wmma::row_major> a0, a1;
                wmma::fragment<wmma::matrix_b, 16, 16, 16, __nv_bfloat16, wmma::row_major> b0, b1;
                wmma::load_matrix_sync(a0, sHb + (wm2 * 32) * LDHB + k2, LDHB);
                wmma::load_matrix_sync(a1, sHb + (wm2 * 32 + 16) * LDHB + k2, LDHB);
                wmma::load_matrix_sync(b0, sWpr + k2 * LDWPR + wn2 * 32, LDWPR);
                wmma::load_matrix_sync(b1, sWpr + k2 * LDWPR + wn2 * 32 + 16, LDWPR);
                wmma::mma_sync(acc2[0][0], a0, b0, acc2[0][0]);
                wmma::mma_sync(acc2[0][1], a0, b1, acc2[0][1]);
                wmma::mma_sync(acc2[1][0], a1, b0, acc2[1][0]);
                wmma::mma_sync(acc2[1][1], a1, b1, acc2[1][1]);
            }
        }
    }

    // -------- epilogue: out = x3 + mlp + b_pr (stage acc2 over dead X/Wfc area)
    __syncthreads();
    float* S = (float*)smem;                   // [64][260] f32 = 66560 B < 103424 B
    wmma::store_matrix_sync(S + (wm2*32)*LDSE + wn2*32,          acc2[0][0], LDSE, wmma::mem_row_major);
    wmma::store_matrix_sync(S + (wm2*32)*LDSE + wn2*32 + 16,     acc2[0][1], LDSE, wmma::mem_row_major);
    wmma::store_matrix_sync(S + (wm2*32+16)*LDSE + wn2*32,       acc2[1][0], LDSE, wmma::mem_row_major);
    wmma::store_matrix_sync(S + (wm2*32+16)*LDSE + wn2*32 + 16,  acc2[1][1], LDSE, wmma::mem_row_major);
    __syncthreads();
    #pragma unroll
    for (int i = 0; i < 32; i++) {
        int e = tid + i * 512, r = e >> 8, c = e & 255;
        size_t gi = (row0 + r) * DD + c;
        out[gi] = out[gi] + S[r * LDSE + c] + bpr[c];
    }
}

// ---------------------------------------------------------------------------
extern "C" void kernel_launch(void* const* d_in, const int* in_sizes, int n_in,
                              void* d_out, int out_size) {
    const float* x    = (const float*)d_in[0];
    const float* cx   = (const float*)d_in[1];
    const float* ln1w = (const float*)d_in[2];
    const float* ln1b = (const float*)d_in[3];
    // d_in[4]=wq, d_in[5]=bq: unused (uniform softmax over equal logits; V constant over keys)
    const float* wkv  = (const float*)d_in[6];
    const float* bkv  = (const float*)d_in[7];
    const float* wo   = (const float*)d_in[8];
    const float* bo   = (const float*)d_in[9];
    const float* ln2w = (const float*)d_in[10];
    const float* ln2b = (const float*)d_in[11];
    const float* wfc  = (const float*)d_in[12];
    const float* bfc  = (const float*)d_in[13];
    const float* wpr  = (const float*)d_in[14];
    const float* bpr  = (const float*)d_in[15];
    float* out = (float*)d_out;

    cudaFuncSetAttribute(mlp_kernel, cudaFuncAttributeMaxDynamicSharedMemorySize, SMEM_TOTAL);

    prep_kernel<<<512, 256>>>(wfc, wpr, cx, wkv, bkv, wo, bo);
    mlp_kernel<<<2048, 512, SMEM_TOTAL>>>(x, ln1w, ln1b, ln2w, ln2b, bfc, bpr, out);
}

// round 9
// speedup vs baseline: 1.0870x; 1.0303x over previous
#include <cstdint>
#include <cuda_runtime.h>
#include <cuda_bf16.h>
#include <mma.h>
#include <math.h>

using namespace nvcuda;

#define DD  256

// strides (elements)
#define LDXB  264   // X tile bf16 [64 x 256]
#define LDWFC 136   // Wfc pair tile bf16 [256 x 128]
#define LDWPR 264   // Wpr pair tile bf16 [128 x 256]
#define LDHF  132   // Hf f32 [64 x 128]
#define LDHB  136   // Hb bf16 [64 x 128]
#define LDSE  260   // epilogue stage f32 [64 x 256]

// smem layout (bytes)
#define SM_X    0                 // 64*264*2  = 33792
#define SM_WFC  33792             // 256*136*2 = 69632
#define SM_WPR  103424            // 128*264*2 = 67584
#define SM_HF   171008            // 64*132*4  = 33792
#define SM_HB   204800            // 64*136*2  = 17408
#define SMEM_TOTAL 222208

__device__ __nv_bfloat16 g_wfcb[256 * 1024];   // [k=256, n=1024] row-major
__device__ __nv_bfloat16 g_wprb[1024 * 256];   // [k=1024, n=256] row-major
__device__ float g_yo[1024 * DD];

// ---------------------------------------------------------------------------
__device__ __forceinline__ void cp16(void* sdst, const void* gsrc) {
    unsigned s = (unsigned)__cvta_generic_to_shared(sdst);
    asm volatile("cp.async.cg.shared.global [%0], [%1], 16;" :: "r"(s), "l"(gsrc));
}
#define CP_COMMIT() asm volatile("cp.async.commit_group;" ::: "memory")
#define CP_WAIT0()  asm volatile("cp.async.wait_group 0;" ::: "memory")
#define BARP()        asm volatile("bar.sync 1, 256;" ::: "memory")   // producer team
#define BARC()        asm volatile("bar.sync 2, 256;" ::: "memory")   // consumer team
#define FREE_WAIT()   asm volatile("bar.sync 3, 512;" ::: "memory")
#define FREE_ARRIVE() asm volatile("bar.arrive 3, 512;" ::: "memory")
#define FULL_WAIT()   asm volatile("bar.sync 4, 512;" ::: "memory")
#define FULL_ARRIVE() asm volatile("bar.arrive 4, 512;" ::: "memory")

// ---------------------------------------------------------------------------
// prep: blocks 0-255 convert weights fp32->bf16; blocks 256-511 compute yo.
// ---------------------------------------------------------------------------
__global__ void prep_kernel(const float* __restrict__ wfc, const float* __restrict__ wpr,
                            const float* __restrict__ cx,  const float* __restrict__ wkv,
                            const float* __restrict__ bkv, const float* __restrict__ wo,
                            const float* __restrict__ bo) {
    __shared__ float sCX[4][DD];
    __shared__ float sV[4][DD];
    int tid = threadIdx.x;
    if (blockIdx.x < 256) {
        int i = blockIdx.x * 256 + tid;
        float4 a = ((const float4*)wfc)[i];
        ((__nv_bfloat162*)g_wfcb)[i * 2]     = __floats2bfloat162_rn(a.x, a.y);
        ((__nv_bfloat162*)g_wfcb)[i * 2 + 1] = __floats2bfloat162_rn(a.z, a.w);
        float4 b = ((const float4*)wpr)[i];
        ((__nv_bfloat162*)g_wprb)[i * 2]     = __floats2bfloat162_rn(b.x, b.y);
        ((__nv_bfloat162*)g_wprb)[i * 2 + 1] = __floats2bfloat162_rn(b.z, b.w);
        return;
    }
    int r0 = (blockIdx.x - 256) * 4;
    #pragma unroll
    for (int i = 0; i < 4; i++) sCX[i][tid] = cx[(r0 + i) * DD + tid];
    __syncthreads();
    float acc[4];
    #pragma unroll
    for (int i = 0; i < 4; i++) acc[i] = bkv[DD + tid];
    for (int c = 0; c < DD; c++) {
        float w = wkv[c * 512 + DD + tid];
        #pragma unroll
        for (int i = 0; i < 4; i++) acc[i] += sCX[i][c] * w;
    }
    #pragma unroll
    for (int i = 0; i < 4; i++) sV[i][tid] = acc[i];
    __syncthreads();
    float a2[4];
    #pragma unroll
    for (int i = 0; i < 4; i++) a2[i] = bo[tid];
    for (int k = 0; k < DD; k++) {
        float w = wo[k * DD + tid];
        #pragma unroll
        for (int i = 0; i < 4; i++) a2[i] += sV[i][k] * w;
    }
    #pragma unroll
    for (int i = 0; i < 4; i++) g_yo[(r0 + i) * DD + tid] = a2[i];
}

// ---------------------------------------------------------------------------
// Fused LN -> warp-specialized MLP.  64 rows/block, grid 2048, 512 threads.
// Producers (warps 0-7): GEMM1(p) -> gelu -> Hb.  Consumers (8-15): GEMM2(p).
// ---------------------------------------------------------------------------
__global__ void __launch_bounds__(512, 1)
mlp_kernel(const float* __restrict__ x,
           const float* __restrict__ ln1w, const float* __restrict__ ln1b,
           const float* __restrict__ ln2w, const float* __restrict__ ln2b,
           const float* __restrict__ bfc,  const float* __restrict__ bpr,
           float* __restrict__ out) {
    extern __shared__ char smem[];
    __nv_bfloat16* sXb  = (__nv_bfloat16*)(smem + SM_X);
    __nv_bfloat16* sWfc = (__nv_bfloat16*)(smem + SM_WFC);
    __nv_bfloat16* sWpr = (__nv_bfloat16*)(smem + SM_WPR);
    float*         sHf  = (float*)        (smem + SM_HF);
    __nv_bfloat16* sHb  = (__nv_bfloat16*)(smem + SM_HB);

    int tid  = threadIdx.x;
    int warp = tid >> 5;
    int lane = tid & 31;
    size_t row0 = (size_t)blockIdx.x * 64;

    // team-local preloads of tile p=0 (overlap with LN)
    if (warp < 8) {
        #pragma unroll
        for (int t = 0; t < 16; t++) {
            int idx = tid + t * 256, r = idx >> 4, c8 = idx & 15;
            cp16((char*)sWfc + (r * LDWFC + c8 * 8) * 2, g_wfcb + (size_t)r * 1024 + c8 * 8);
        }
    } else {
        #pragma unroll
        for (int t = 0; t < 16; t++) {
            int idx = (tid - 256) + t * 256, r = idx >> 5, c8 = idx & 31;
            cp16((char*)sWpr + (r * LDWPR + c8 * 8) * 2, g_wprb + (size_t)r * 256 + c8 * 8);
        }
    }
    CP_COMMIT();

    // -------- LN phase: 4 rows/warp; fp32 x3 -> out, bf16 X -> sXb
    {
        float lw1[8], lb1[8], lw2[8], lb2[8], yo[8];
        float4 a, b;
        a = ((const float4*)ln1w)[lane*2]; b = ((const float4*)ln1w)[lane*2+1];
        lw1[0]=a.x;lw1[1]=a.y;lw1[2]=a.z;lw1[3]=a.w;lw1[4]=b.x;lw1[5]=b.y;lw1[6]=b.z;lw1[7]=b.w;
        a = ((const float4*)ln1b)[lane*2]; b = ((const float4*)ln1b)[lane*2+1];
        lb1[0]=a.x;lb1[1]=a.y;lb1[2]=a.z;lb1[3]=a.w;lb1[4]=b.x;lb1[5]=b.y;lb1[6]=b.z;lb1[7]=b.w;
        a = ((const float4*)ln2w)[lane*2]; b = ((const float4*)ln2w)[lane*2+1];
        lw2[0]=a.x;lw2[1]=a.y;lw2[2]=a.z;lw2[3]=a.w;lw2[4]=b.x;lw2[5]=b.y;lw2[6]=b.z;lw2[7]=b.w;
        a = ((const float4*)ln2b)[lane*2]; b = ((const float4*)ln2b)[lane*2+1];
        lb2[0]=a.x;lb2[1]=a.y;lb2[2]=a.z;lb2[3]=a.w;lb2[4]=b.x;lb2[5]=b.y;lb2[6]=b.z;lb2[7]=b.w;
        const float* yor = g_yo + (row0 >> 7) * DD;
        a = ((const float4*)yor)[lane*2]; b = ((const float4*)yor)[lane*2+1];
        yo[0]=a.x;yo[1]=a.y;yo[2]=a.z;yo[3]=a.w;yo[4]=b.x;yo[5]=b.y;yo[6]=b.z;yo[7]=b.w;

        for (int rr = 0; rr < 4; rr++) {
            int row = warp * 4 + rr;
            const float4* xr = (const float4*)(x + (row0 + row) * DD);
            float v[8];
            { float4 u0 = xr[lane*2], u1 = xr[lane*2+1];
              v[0]=u0.x;v[1]=u0.y;v[2]=u0.z;v[3]=u0.w;v[4]=u1.x;v[5]=u1.y;v[6]=u1.z;v[7]=u1.w; }
            float s = 0.f, q = 0.f;
            #pragma unroll
            for (int j = 0; j < 8; j++) { s += v[j]; q += v[j]*v[j]; }
            #pragma unroll
            for (int o = 16; o > 0; o >>= 1) { s += __shfl_xor_sync(~0u,s,o); q += __shfl_xor_sync(~0u,q,o); }
            float mu = s * (1.f/DD);
            float rs = rsqrtf(q * (1.f/DD) - mu*mu + 1e-5f);
            float tv[8]; s = 0.f; q = 0.f;
            #pragma unroll
            for (int j = 0; j < 8; j++) {
                tv[j] = (v[j]-mu)*rs*lw1[j] + lb1[j] + yo[j];
                s += tv[j]; q += tv[j]*tv[j];
            }
            #pragma unroll
            for (int o = 16; o > 0; o >>= 1) { s += __shfl_xor_sync(~0u,s,o); q += __shfl_xor_sync(~0u,q,o); }
            float mu2 = s * (1.f/DD);
            float rs2 = rsqrtf(q * (1.f/DD) - mu2*mu2 + 1e-5f);
            #pragma unroll
            for (int j = 0; j < 8; j++) v[j] = (tv[j]-mu2)*rs2*lw2[j] + lb2[j];

            float* orow = out + (row0 + row) * DD;
            ((float4*)orow)[lane*2]   = make_float4(v[0],v[1],v[2],v[3]);
            ((float4*)orow)[lane*2+1] = make_float4(v[4],v[5],v[6],v[7]);

            __nv_bfloat162 p0 = __floats2bfloat162_rn(v[0],v[1]);
            __nv_bfloat162 p1 = __floats2bfloat162_rn(v[2],v[3]);
            __nv_bfloat162 p2 = __floats2bfloat162_rn(v[4],v[5]);
            __nv_bfloat162 p3 = __floats2bfloat162_rn(v[6],v[7]);
            uint4 pk;
            pk.x = *(unsigned*)&p0; pk.y = *(unsigned*)&p1; pk.z = *(unsigned*)&p2; pk.w = *(unsigned*)&p3;
            *(uint4*)(sXb + row * LDXB + lane * 8) = pk;
        }
    }
    __syncthreads();      // sX visible to producers

    if (warp < 8) {
        // =================== PRODUCER: GEMM1 + gelu ===================
        int wm = warp & 1, wn = warp >> 1;     // rows wm*32, cols wn*32 (of 128)
        for (int p = 0; p < 8; p++) {
            CP_WAIT0();
            BARP();                            // all producers' Wfc(p) chunks landed
            wmma::fragment<wmma::accumulator, 16, 16, 16, float> c00, c01, c10, c11;
            wmma::fill_fragment(c00, 0.f); wmma::fill_fragment(c01, 0.f);
            wmma::fill_fragment(c10, 0.f); wmma::fill_fragment(c11, 0.f);
            const __nv_bfloat16* Xb = sXb + (wm * 32) * LDXB;
            #pragma unroll
            for (int k = 0; k < 256; k += 16) {
                wmma::fragment<wmma::matrix_a, 16, 16, 16, __nv_bfloat16, wmma::row_major> a0, a1;
                wmma::fragment<wmma::matrix_b, 16, 16, 16, __nv_bfloat16, wmma::row_major> b0, b1;
                wmma::load_matrix_sync(a0, Xb + k, LDXB);
                wmma::load_matrix_sync(a1, Xb + 16 * LDXB + k, LDXB);
                wmma::load_matrix_sync(b0, sWfc + k * LDWFC + wn * 32, LDWFC);
                wmma::load_matrix_sync(b1, sWfc + k * LDWFC + wn * 32 + 16, LDWFC);
                wmma::mma_sync(c00, a0, b0, c00);
                wmma::mma_sync(c01, a0, b1, c01);
                wmma::mma_sync(c10, a1, b0, c10);
                wmma::mma_sync(c11, a1, b1, c11);
            }
            BARP();                            // all producers done reading Wfc(p)
            if (p < 7) {                       // refill Wfc(p+1)
                #pragma unroll
                for (int t = 0; t < 16; t++) {
                    int idx = tid + t * 256, r = idx >> 4, c8 = idx & 15;
                    cp16((char*)sWfc + (r * LDWFC + c8 * 8) * 2,
                         g_wfcb + (size_t)r * 1024 + (p + 1) * 128 + c8 * 8);
                }
                CP_COMMIT();
            }
            // stage via warp-private Hf, gelu in regs
            float* Hf = sHf + (wm * 32) * LDHF + wn * 32;
            wmma::store_matrix_sync(Hf,                 c00, LDHF, wmma::mem_row_major);
            wmma::store_matrix_sync(Hf + 16,            c01, LDHF, wmma::mem_row_major);
            wmma::store_matrix_sync(Hf + 16 * LDHF,     c10, LDHF, wmma::mem_row_major);
            wmma::store_matrix_sync(Hf + 16 * LDHF + 16,c11, LDHF, wmma::mem_row_major);
            __syncwarp();
            const float* Hr = sHf + (wm * 32 + lane) * LDHF + wn * 32;
            const float* bf = bfc + p * 128 + wn * 32;
            unsigned u[16];
            #pragma unroll
            for (int j = 0; j < 8; j++) {
                float4 f = *(const float4*)(Hr + j * 4);
                f.x += bf[j*4+0]; f.y += bf[j*4+1]; f.z += bf[j*4+2]; f.w += bf[j*4+3];
                f.x = 0.5f*f.x*(1.f+erff(f.x*0.70710678118654752f));
                f.y = 0.5f*f.y*(1.f+erff(f.y*0.70710678118654752f));
                f.z = 0.5f*f.z*(1.f+erff(f.z*0.70710678118654752f));
                f.w = 0.5f*f.w*(1.f+erff(f.w*0.70710678118654752f));
                __nv_bfloat162 q0 = __floats2bfloat162_rn(f.x, f.y);
                __nv_bfloat162 q1 = __floats2bfloat162_rn(f.z, f.w);
                u[j*2]   = *(unsigned*)&q0;
                u[j*2+1] = *(unsigned*)&q1;
            }
            if (p > 0) FREE_WAIT();            // consumer done reading Hb(p-1)
            uint4* Hw = (uint4*)(sHb + (wm * 32 + lane) * LDHB + wn * 32);
            #pragma unroll
            for (int q = 0; q < 4; q++)
                Hw[q] = make_uint4(u[q*4], u[q*4+1], u[q*4+2], u[q*4+3]);
            __threadfence_block();
            FULL_ARRIVE();
        }
    } else {
        // =================== CONSUMER: GEMM2, acc in regs ===================
        int cc = warp - 8;
        int cm = cc & 1, cn = cc >> 1;         // rows cm*32, cols cn*64
        wmma::fragment<wmma::accumulator, 16, 16, 16, float> acc2[2][4];
        #pragma unroll
        for (int m = 0; m < 2; m++)
            #pragma unroll
            for (int n = 0; n < 4; n++) wmma::fill_fragment(acc2[m][n], 0.f);

        for (int p = 0; p < 8; p++) {
            CP_WAIT0();
            BARC();                            // all consumers' Wpr(p) chunks landed
            FULL_WAIT();                       // Hb(p) published
            #pragma unroll
            for (int k2 = 0; k2 < 128; k2 += 16) {
                wmma::fragment<wmma::matrix_a, 16, 16, 16, __nv_bfloat16, wmma::row_major> a0, a1;
                wmma::load_matrix_sync(a0, sHb + (cm * 32) * LDHB + k2, LDHB);
                wmma::load_matrix_sync(a1, sHb + (cm * 32 + 16) * LDHB + k2, LDHB);
                #pragma unroll
                for (int n = 0; n < 4; n++) {
                    wmma::fragment<wmma::matrix_b, 16, 16, 16, __nv_bfloat16, wmma::row_major> b;
                    wmma::load_matrix_sync(b, sWpr + k2 * LDWPR + cn * 64 + n * 16, LDWPR);
                    wmma::mma_sync(acc2[0][n], a0, b, acc2[0][n]);
                    wmma::mma_sync(acc2[1][n], a1, b, acc2[1][n]);
                }
            }
            FREE_ARRIVE();                     // done reading Hb(p)
            BARC();                            // all consumers done reading Wpr(p)
            if (p < 7) {                       // refill Wpr(p+1)
                #pragma unroll
                for (int t = 0; t < 16; t++) {
                    int idx = (tid - 256) + t * 256, r = idx >> 5, c8 = idx & 31;
                    cp16((char*)sWpr + (r * LDWPR + c8 * 8) * 2,
                         g_wprb + ((size_t)((p + 1) * 128 + r)) * 256 + c8 * 8);
                }
                CP_COMMIT();
            }
        }
        // stage acc2 to smem (over dead Wfc region)
        float* S = (float*)(smem + SM_WFC);
        #pragma unroll
        for (int n = 0; n < 4; n++) {
            wmma::store_matrix_sync(S + (cm*32)*LDSE + cn*64 + n*16,      acc2[0][n], LDSE, wmma::mem_row_major);
            wmma::store_matrix_sync(S + (cm*32+16)*LDSE + cn*64 + n*16,   acc2[1][n], LDSE, wmma::mem_row_major);
        }
    }

    __syncthreads();
    // -------- epilogue: out = x3 + mlp + b_pr
    const float* S = (const float*)(smem + SM_WFC);
    #pragma unroll
    for (int i = 0; i < 32; i++) {
        int e = tid + i * 512, r = e >> 8, c = e & 255;
        size_t gi = (row0 + r) * DD + c;
        out[gi] = out[gi] + S[r * LDSE + c] + bpr[c];
    }
}

// ---------------------------------------------------------------------------
extern "C" void kernel_launch(void* const* d_in, const int* in_sizes, int n_in,
                              void* d_out, int out_size) {
    const float* x    = (const float*)d_in[0];
    const float* cx   = (const float*)d_in[1];
    const float* ln1w = (const float*)d_in[2];
    const float* ln1b = (const float*)d_in[3];
    // d_in[4]=wq, d_in[5]=bq: unused (uniform softmax over equal logits; V constant over keys)
    const float* wkv  = (const float*)d_in[6];
    const float* bkv  = (const float*)d_in[7];
    const float* wo   = (const float*)d_in[8];
    const float* bo   = (const float*)d_in[9];
    const float* ln2w = (const float*)d_in[10];
    const float* ln2b = (const float*)d_in[11];
    const float* wfc  = (const float*)d_in[12];
    const float* bfc  = (const float*)d_in[13];
    const float* wpr  = (const float*)d_in[14];
    const float* bpr  = (const float*)d_in[15];
    float* out = (float*)d_out;

    cudaFuncSetAttribute(mlp_kernel, cudaFuncAttributeMaxDynamicSharedMemorySize, SMEM_TOTAL);

    prep_kernel<<<512, 256>>>(wfc, wpr, cx, wkv, bkv, wo, bo);
    mlp_kernel<<<2048, 512, SMEM_TOTAL>>>(x, ln1w, ln1b, ln2w, ln2b, bfc, bpr, out);
}

// round 10
// speedup vs baseline: 1.2782x; 1.1759x over previous
#include <cstdint>
#include <cuda_runtime.h>
#include <cuda_bf16.h>
#include <mma.h>
#include <math.h>

using namespace nvcuda;

#define DD 256

#define LDA 40     // A tile stride (bf16): 32 + 8 pad
#define LDB 136    // B tile stride (bf16): 128 + 8 pad
#define LDS 132    // epilogue staging stride (f32)

// one contiguous smem arena per GEMM CTA: 2 A bufs + 2 B bufs; epilogue reuses it
#define OFF_A0 0
#define OFF_A1 10240          // 128*LDA*2
#define OFF_B0 20480
#define OFF_B1 29184          // + 32*LDB*2
#define SMEM_GEMM 37888       // >= 64*LDS*4 = 33792 for epilogue staging

__device__ __nv_bfloat16 g_wfcb[256 * 1024];     // [k=256,  n=1024]
__device__ __nv_bfloat16 g_wprb[1024 * 256];     // [k=1024, n=256]
__device__ float         g_yo[1024 * DD];
__device__ __nv_bfloat16 g_xb[131072 * 256];     // x3 in bf16 (67 MB)
__device__ __nv_bfloat16 g_hb[(size_t)131072 * 1024];  // gelu(h) bf16 (268 MB)

// ---------------------------------------------------------------------------
__device__ __forceinline__ void cp16(void* sdst, const void* gsrc) {
    unsigned s = (unsigned)__cvta_generic_to_shared(sdst);
    asm volatile("cp.async.cg.shared.global [%0], [%1], 16;" :: "r"(s), "l"(gsrc));
}
#define CP_COMMIT() asm volatile("cp.async.commit_group;" ::: "memory")
#define CP_WAIT0()  asm volatile("cp.async.wait_group 0;" ::: "memory")

__device__ __forceinline__ float gelu_exact(float v) {
    return 0.5f * v * (1.f + erff(v * 0.70710678118654752f));
}

// ---------------------------------------------------------------------------
// prep: blocks 0-255 convert weights fp32->bf16; blocks 256-511 compute yo.
// yo[b,a,:] = ((cx @ wkv)[:, D:2D] + bkv[D:2D]) @ wo + bo
// ---------------------------------------------------------------------------
__global__ void prep_kernel(const float* __restrict__ wfc, const float* __restrict__ wpr,
                            const float* __restrict__ cx,  const float* __restrict__ wkv,
                            const float* __restrict__ bkv, const float* __restrict__ wo,
                            const float* __restrict__ bo) {
    __shared__ float sCX[4][DD];
    __shared__ float sV[4][DD];
    int tid = threadIdx.x;
    if (blockIdx.x < 256) {
        int i = blockIdx.x * 256 + tid;
        float4 a = ((const float4*)wfc)[i];
        ((__nv_bfloat162*)g_wfcb)[i * 2]     = __floats2bfloat162_rn(a.x, a.y);
        ((__nv_bfloat162*)g_wfcb)[i * 2 + 1] = __floats2bfloat162_rn(a.z, a.w);
        float4 b = ((const float4*)wpr)[i];
        ((__nv_bfloat162*)g_wprb)[i * 2]     = __floats2bfloat162_rn(b.x, b.y);
        ((__nv_bfloat162*)g_wprb)[i * 2 + 1] = __floats2bfloat162_rn(b.z, b.w);
        return;
    }
    int r0 = (blockIdx.x - 256) * 4;
    #pragma unroll
    for (int i = 0; i < 4; i++) sCX[i][tid] = cx[(r0 + i) * DD + tid];
    __syncthreads();
    float acc[4];
    #pragma unroll
    for (int i = 0; i < 4; i++) acc[i] = bkv[DD + tid];
    for (int c = 0; c < DD; c++) {
        float w = wkv[c * 512 + DD + tid];
        #pragma unroll
        for (int i = 0; i < 4; i++) acc[i] += sCX[i][c] * w;
    }
    #pragma unroll
    for (int i = 0; i < 4; i++) sV[i][tid] = acc[i];
    __syncthreads();
    float a2[4];
    #pragma unroll
    for (int i = 0; i < 4; i++) a2[i] = bo[tid];
    for (int k = 0; k < DD; k++) {
        float w = wo[k * DD + tid];
        #pragma unroll
        for (int i = 0; i < 4; i++) a2[i] += sV[i][k] * w;
    }
    #pragma unroll
    for (int i = 0; i < 4; i++) g_yo[(r0 + i) * DD + tid] = a2[i];
}

// ---------------------------------------------------------------------------
// LN: x3 = LN2(LN1(x)+yo) -> out (fp32, residual base) and g_xb (bf16 GEMM A)
// One warp per row; 8 rows/block; grid 16384.
// ---------------------------------------------------------------------------
__global__ void __launch_bounds__(256)
ln_kernel(const float* __restrict__ x,
          const float* __restrict__ ln1w, const float* __restrict__ ln1b,
          const float* __restrict__ ln2w, const float* __restrict__ ln2b,
          float* __restrict__ out) {
    int warp = threadIdx.x >> 5;
    int lane = threadIdx.x & 31;
    size_t row = (size_t)blockIdx.x * 8 + warp;

    float lw1[8], lb1[8], lw2[8], lb2[8], yo[8];
    {
        float4 a, b;
        a = ((const float4*)ln1w)[lane*2]; b = ((const float4*)ln1w)[lane*2+1];
        lw1[0]=a.x;lw1[1]=a.y;lw1[2]=a.z;lw1[3]=a.w;lw1[4]=b.x;lw1[5]=b.y;lw1[6]=b.z;lw1[7]=b.w;
        a = ((const float4*)ln1b)[lane*2]; b = ((const float4*)ln1b)[lane*2+1];
        lb1[0]=a.x;lb1[1]=a.y;lb1[2]=a.z;lb1[3]=a.w;lb1[4]=b.x;lb1[5]=b.y;lb1[6]=b.z;lb1[7]=b.w;
        a = ((const float4*)ln2w)[lane*2]; b = ((const float4*)ln2w)[lane*2+1];
        lw2[0]=a.x;lw2[1]=a.y;lw2[2]=a.z;lw2[3]=a.w;lw2[4]=b.x;lw2[5]=b.y;lw2[6]=b.z;lw2[7]=b.w;
        a = ((const float4*)ln2b)[lane*2]; b = ((const float4*)ln2b)[lane*2+1];
        lb2[0]=a.x;lb2[1]=a.y;lb2[2]=a.z;lb2[3]=a.w;lb2[4]=b.x;lb2[5]=b.y;lb2[6]=b.z;lb2[7]=b.w;
        const float* yor = g_yo + (row >> 7) * DD;
        a = ((const float4*)yor)[lane*2]; b = ((const float4*)yor)[lane*2+1];
        yo[0]=a.x;yo[1]=a.y;yo[2]=a.z;yo[3]=a.w;yo[4]=b.x;yo[5]=b.y;yo[6]=b.z;yo[7]=b.w;
    }
    const float4* xr = (const float4*)(x + row * DD);
    float v[8];
    { float4 u0 = xr[lane*2], u1 = xr[lane*2+1];
      v[0]=u0.x;v[1]=u0.y;v[2]=u0.z;v[3]=u0.w;v[4]=u1.x;v[5]=u1.y;v[6]=u1.z;v[7]=u1.w; }
    float s = 0.f, q = 0.f;
    #pragma unroll
    for (int j = 0; j < 8; j++) { s += v[j]; q += v[j]*v[j]; }
    #pragma unroll
    for (int o = 16; o > 0; o >>= 1) { s += __shfl_xor_sync(~0u,s,o); q += __shfl_xor_sync(~0u,q,o); }
    float mu = s * (1.f/DD);
    float rs = rsqrtf(q * (1.f/DD) - mu*mu + 1e-5f);
    float tv[8]; s = 0.f; q = 0.f;
    #pragma unroll
    for (int j = 0; j < 8; j++) {
        tv[j] = (v[j]-mu)*rs*lw1[j] + lb1[j] + yo[j];
        s += tv[j]; q += tv[j]*tv[j];
    }
    #pragma unroll
    for (int o = 16; o > 0; o >>= 1) { s += __shfl_xor_sync(~0u,s,o); q += __shfl_xor_sync(~0u,q,o); }
    float mu2 = s * (1.f/DD);
    float rs2 = rsqrtf(q * (1.f/DD) - mu2*mu2 + 1e-5f);
    #pragma unroll
    for (int j = 0; j < 8; j++) v[j] = (tv[j]-mu2)*rs2*lw2[j] + lb2[j];

    float* orow = out + row * DD;
    ((float4*)orow)[lane*2]   = make_float4(v[0],v[1],v[2],v[3]);
    ((float4*)orow)[lane*2+1] = make_float4(v[4],v[5],v[6],v[7]);

    __nv_bfloat162 p0 = __floats2bfloat162_rn(v[0],v[1]);
    __nv_bfloat162 p1 = __floats2bfloat162_rn(v[2],v[3]);
    __nv_bfloat162 p2 = __floats2bfloat162_rn(v[4],v[5]);
    __nv_bfloat162 p3 = __floats2bfloat162_rn(v[6],v[7]);
    uint4 pk;
    pk.x = *(unsigned*)&p0; pk.y = *(unsigned*)&p1; pk.z = *(unsigned*)&p2; pk.w = *(unsigned*)&p3;
    *(uint4*)(g_xb + row * DD + lane * 8) = pk;
}

// ---------------------------------------------------------------------------
// GEMM1: g_hb = gelu(g_xb @ Wfc + bfc)    [131072,256]x[256,1024]
// 128x128 tile, 256 threads, 2 CTAs/SM, double-buffered cp.async.
// ---------------------------------------------------------------------------
__global__ void __launch_bounds__(256, 2)
gemm1_kernel(const float* __restrict__ bfc) {
    __shared__ __align__(16) char sm[SMEM_GEMM];
    __nv_bfloat16* sA[2] = { (__nv_bfloat16*)(sm + OFF_A0), (__nv_bfloat16*)(sm + OFF_A1) };
    __nv_bfloat16* sB[2] = { (__nv_bfloat16*)(sm + OFF_B0), (__nv_bfloat16*)(sm + OFF_B1) };

    int tid  = threadIdx.x;
    int warp = tid >> 5;
    int wm = warp >> 1, wn = warp & 1;
    size_t row0 = (size_t)(blockIdx.x >> 3) * 128;
    int col0 = (blockIdx.x & 7) * 128;

    wmma::fragment<wmma::accumulator, 16, 16, 16, float> c0[4], c1[4];
    #pragma unroll
    for (int n = 0; n < 4; n++) { wmma::fill_fragment(c0[n], 0.f); wmma::fill_fragment(c1[n], 0.f); }

    // prefetch kt=0
    #pragma unroll
    for (int j = 0; j < 2; j++) {
        int c = tid + j * 256, r = c >> 2, q = c & 3;
        cp16(sA[0] + r * LDA + q * 8, g_xb + (row0 + r) * 256 + q * 8);
    }
    #pragma unroll
    for (int j = 0; j < 2; j++) {
        int c = tid + j * 256, r = c >> 4, q = c & 15;
        cp16(sB[0] + r * LDB + q * 8, g_wfcb + (size_t)r * 1024 + col0 + q * 8);
    }
    CP_COMMIT();

    for (int kt = 0; kt < 8; kt++) {
        CP_WAIT0();
        __syncthreads();
        if (kt < 7) {
            int nb = (kt + 1) & 1;
            #pragma unroll
            for (int j = 0; j < 2; j++) {
                int c = tid + j * 256, r = c >> 2, q = c & 3;
                cp16(sA[nb] + r * LDA + q * 8, g_xb + (row0 + r) * 256 + (kt + 1) * 32 + q * 8);
            }
            #pragma unroll
            for (int j = 0; j < 2; j++) {
                int c = tid + j * 256, r = c >> 4, q = c & 15;
                cp16(sB[nb] + r * LDB + q * 8, g_wfcb + (size_t)((kt + 1) * 32 + r) * 1024 + col0 + q * 8);
            }
            CP_COMMIT();
        }
        const __nv_bfloat16* Ab = sA[kt & 1] + (wm * 32) * LDA;
        const __nv_bfloat16* Bb = sB[kt & 1] + wn * 64;
        #pragma unroll
        for (int ks = 0; ks < 32; ks += 16) {
            wmma::fragment<wmma::matrix_a, 16, 16, 16, __nv_bfloat16, wmma::row_major> a0, a1;
            wmma::load_matrix_sync(a0, Ab + ks, LDA);
            wmma::load_matrix_sync(a1, Ab + 16 * LDA + ks, LDA);
            #pragma unroll
            for (int n = 0; n < 4; n++) {
                wmma::fragment<wmma::matrix_b, 16, 16, 16, __nv_bfloat16, wmma::row_major> b;
                wmma::load_matrix_sync(b, Bb + ks * LDB + n * 16, LDB);
                wmma::mma_sync(c0[n], a0, b, c0[n]);
                wmma::mma_sync(c1[n], a1, b, c1[n]);
            }
        }
    }

    // epilogue: bias + gelu -> bf16 g_hb, staged through smem in 2 row passes
    float* S = (float*)sm;
    for (int p = 0; p < 2; p++) {
        __syncthreads();
        if ((wm >> 1) == p) {
            float* Sp = S + ((wm & 1) * 32) * LDS + wn * 64;
            #pragma unroll
            for (int n = 0; n < 4; n++) {
                wmma::store_matrix_sync(Sp + n * 16,            c0[n], LDS, wmma::mem_row_major);
                wmma::store_matrix_sync(Sp + 16 * LDS + n * 16, c1[n], LDS, wmma::mem_row_major);
            }
        }
        __syncthreads();
        #pragma unroll
        for (int j = 0; j < 4; j++) {
            int cc = tid + j * 256, r = cc >> 4, q = cc & 15;
            const float* Sr = S + r * LDS + q * 8;
            float4 f0 = *(const float4*)(Sr);
            float4 f1 = *(const float4*)(Sr + 4);
            const float* bf = bfc + col0 + q * 8;
            f0.x = gelu_exact(f0.x + bf[0]); f0.y = gelu_exact(f0.y + bf[1]);
            f0.z = gelu_exact(f0.z + bf[2]); f0.w = gelu_exact(f0.w + bf[3]);
            f1.x = gelu_exact(f1.x + bf[4]); f1.y = gelu_exact(f1.y + bf[5]);
            f1.z = gelu_exact(f1.z + bf[6]); f1.w = gelu_exact(f1.w + bf[7]);
            __nv_bfloat162 q0 = __floats2bfloat162_rn(f0.x, f0.y);
            __nv_bfloat162 q1 = __floats2bfloat162_rn(f0.z, f0.w);
            __nv_bfloat162 q2 = __floats2bfloat162_rn(f1.x, f1.y);
            __nv_bfloat162 q3 = __floats2bfloat162_rn(f1.z, f1.w);
            uint4 pk;
            pk.x = *(unsigned*)&q0; pk.y = *(unsigned*)&q1;
            pk.z = *(unsigned*)&q2; pk.w = *(unsigned*)&q3;
            *(uint4*)(g_hb + (row0 + p * 64 + r) * 1024 + col0 + q * 8) = pk;
        }
    }
}

// ---------------------------------------------------------------------------
// GEMM2: out = x3(out) + g_hb @ Wpr + bpr    [131072,1024]x[1024,256]
// ---------------------------------------------------------------------------
__global__ void __launch_bounds__(256, 2)
gemm2_kernel(const float* __restrict__ bpr, float* __restrict__ out) {
    __shared__ __align__(16) char sm[SMEM_GEMM];
    __nv_bfloat16* sA[2] = { (__nv_bfloat16*)(sm + OFF_A0), (__nv_bfloat16*)(sm + OFF_A1) };
    __nv_bfloat16* sB[2] = { (__nv_bfloat16*)(sm + OFF_B0), (__nv_bfloat16*)(sm + OFF_B1) };

    int tid  = threadIdx.x;
    int warp = tid >> 5;
    int wm = warp >> 1, wn = warp & 1;
    size_t row0 = (size_t)(blockIdx.x >> 1) * 128;
    int col0 = (blockIdx.x & 1) * 128;

    wmma::fragment<wmma::accumulator, 16, 16, 16, float> c0[4], c1[4];
    #pragma unroll
    for (int n = 0; n < 4; n++) { wmma::fill_fragment(c0[n], 0.f); wmma::fill_fragment(c1[n], 0.f); }

    #pragma unroll
    for (int j = 0; j < 2; j++) {
        int c = tid + j * 256, r = c >> 2, q = c & 3;
        cp16(sA[0] + r * LDA + q * 8, g_hb + (row0 + r) * 1024 + q * 8);
    }
    #pragma unroll
    for (int j = 0; j < 2; j++) {
        int c = tid + j * 256, r = c >> 4, q = c & 15;
        cp16(sB[0] + r * LDB + q * 8, g_wprb + (size_t)r * 256 + col0 + q * 8);
    }
    CP_COMMIT();

    for (int kt = 0; kt < 32; kt++) {
        CP_WAIT0();
        __syncthreads();
        if (kt < 31) {
            int nb = (kt + 1) & 1;
            #pragma unroll
            for (int j = 0; j < 2; j++) {
                int c = tid + j * 256, r = c >> 2, q = c & 3;
                cp16(sA[nb] + r * LDA + q * 8, g_hb + (row0 + r) * 1024 + (kt + 1) * 32 + q * 8);
            }
            #pragma unroll
            for (int j = 0; j < 2; j++) {
                int c = tid + j * 256, r = c >> 4, q = c & 15;
                cp16(sB[nb] + r * LDB + q * 8, g_wprb + (size_t)((kt + 1) * 32 + r) * 256 + col0 + q * 8);
            }
            CP_COMMIT();
        }
        const __nv_bfloat16* Ab = sA[kt & 1] + (wm * 32) * LDA;
        const __nv_bfloat16* Bb = sB[kt & 1] + wn * 64;
        #pragma unroll
        for (int ks = 0; ks < 32; ks += 16) {
            wmma::fragment<wmma::matrix_a, 16, 16, 16, __nv_bfloat16, wmma::row_major> a0, a1;
            wmma::load_matrix_sync(a0, Ab + ks, LDA);
            wmma::load_matrix_sync(a1, Ab + 16 * LDA + ks, LDA);
            #pragma unroll
            for (int n = 0; n < 4; n++) {
                wmma::fragment<wmma::matrix_b, 16, 16, 16, __nv_bfloat16, wmma::row_major> b;
                wmma::load_matrix_sync(b, Bb + ks * LDB + n * 16, LDB);
                wmma::mma_sync(c0[n], a0, b, c0[n]);
                wmma::mma_sync(c1[n], a1, b, c1[n]);
            }
        }
    }

    // epilogue: out = x3(out) + acc + bpr, staged in 2 row passes
    float* S = (float*)sm;
    for (int p = 0; p < 2; p++) {
        __syncthreads();
        if ((wm >> 1) == p) {
            float* Sp = S + ((wm & 1) * 32) * LDS + wn * 64;
            #pragma unroll
            for (int n = 0; n < 4; n++) {
                wmma::store_matrix_sync(Sp + n * 16,            c0[n], LDS, wmma::mem_row_major);
                wmma::store_matrix_sync(Sp + 16 * LDS + n * 16, c1[n], LDS, wmma::mem_row_major);
            }
        }
        __syncthreads();
        #pragma unroll
        for (int j = 0; j < 4; j++) {
            int cc = tid + j * 256, r = cc >> 4, q = cc & 15;
            const float* Sr = S + r * LDS + q * 8;
            float* og = out + (row0 + p * 64 + r) * DD + col0 + q * 8;
            const float* bp = bpr + col0 + q * 8;
            float4 f0 = *(const float4*)(Sr);
            float4 f1 = *(const float4*)(Sr + 4);
            float4 x0 = *(const float4*)(og);
            float4 x1 = *(const float4*)(og + 4);
            f0.x += x0.x + bp[0]; f0.y += x0.y + bp[1]; f0.z += x0.z + bp[2]; f0.w += x0.w + bp[3];
            f1.x += x1.x + bp[4]; f1.y += x1.y + bp[5]; f1.z += x1.z + bp[6]; f1.w += x1.w + bp[7];
            *(float4*)(og)     = f0;
            *(float4*)(og + 4) = f1;
        }
    }
}

// ---------------------------------------------------------------------------
extern "C" void kernel_launch(void* const* d_in, const int* in_sizes, int n_in,
                              void* d_out, int out_size) {
    const float* x    = (const float*)d_in[0];
    const float* cx   = (const float*)d_in[1];
    const float* ln1w = (const float*)d_in[2];
    const float* ln1b = (const float*)d_in[3];
    // d_in[4]=wq, d_in[5]=bq: unused (uniform softmax over equal logits; V constant over keys)
    const float* wkv  = (const float*)d_in[6];
    const float* bkv  = (const float*)d_in[7];
    const float* wo   = (const float*)d_in[8];
    const float* bo   = (const float*)d_in[9];
    const float* ln2w = (const float*)d_in[10];
    const float* ln2b = (const float*)d_in[11];
    const float* wfc  = (const float*)d_in[12];
    const float* bfc  = (const float*)d_in[13];
    const float* wpr  = (const float*)d_in[14];
    const float* bpr  = (const float*)d_in[15];
    float* out = (float*)d_out;

    prep_kernel<<<512, 256>>>(wfc, wpr, cx, wkv, bkv, wo, bo);
    ln_kernel<<<16384, 256>>>(x, ln1w, ln1b, ln2w, ln2b, out);
    gemm1_kernel<<<8192, 256>>>(bfc);
    gemm2_kernel<<<2048, 256>>>(bpr, out);
}

// round 11
// speedup vs baseline: 1.3440x; 1.0515x over previous
#include <cstdint>
#include <cuda_runtime.h>
#include <cuda_bf16.h>
#include <mma.h>
#include <math.h>

using namespace nvcuda;

#define DD 256

#define LDA 72     // A stage stride (bf16): 64 + 8 pad
#define LDB 136    // B stage stride (bf16): 128 + 8 pad
#define LDS 132    // epilogue staging stride (f32)

// 3-stage pipeline arena: each stage = A[128x64] + B[64x128] (bf16, padded)
#define ST_A     18432            // 128*72*2
#define ST_B     17408            // 64*136*2
#define ST_BYTES 35840
#define SMEM_PIPE (3 * ST_BYTES)  // 107520; epilogue reuses (128*132*4 = 67584)

__device__ __nv_bfloat16 g_wfcb[256 * 1024];     // [k=256,  n=1024]
__device__ __nv_bfloat16 g_wprb[1024 * 256];     // [k=1024, n=256]
__device__ float         g_yo[1024 * DD];
__device__ __nv_bfloat16 g_xb[131072 * 256];           // x3 bf16
__device__ __nv_bfloat16 g_hb[(size_t)131072 * 1024];  // gelu(h) bf16

// ---------------------------------------------------------------------------
__device__ __forceinline__ void cp16(void* sdst, const void* gsrc) {
    unsigned s = (unsigned)__cvta_generic_to_shared(sdst);
    asm volatile("cp.async.cg.shared.global [%0], [%1], 16;" :: "r"(s), "l"(gsrc));
}
#define CP_COMMIT() asm volatile("cp.async.commit_group;" ::: "memory")
#define CP_WAIT1()  asm volatile("cp.async.wait_group 1;" ::: "memory")
#define CP_WAIT0()  asm volatile("cp.async.wait_group 0;" ::: "memory")

__device__ __forceinline__ float gelu_exact(float v) {
    return 0.5f * v * (1.f + erff(v * 0.70710678118654752f));
}

// ---------------------------------------------------------------------------
// prep: blocks 0-255 convert weights fp32->bf16; blocks 256-511 compute yo.
// yo[b,a,:] = ((cx @ wkv)[:, D:2D] + bkv[D:2D]) @ wo + bo
// ---------------------------------------------------------------------------
__global__ void prep_kernel(const float* __restrict__ wfc, const float* __restrict__ wpr,
                            const float* __restrict__ cx,  const float* __restrict__ wkv,
                            const float* __restrict__ bkv, const float* __restrict__ wo,
                            const float* __restrict__ bo) {
    __shared__ float sCX[4][DD];
    __shared__ float sV[4][DD];
    int tid = threadIdx.x;
    if (blockIdx.x < 256) {
        int i = blockIdx.x * 256 + tid;
        float4 a = ((const float4*)wfc)[i];
        ((__nv_bfloat162*)g_wfcb)[i * 2]     = __floats2bfloat162_rn(a.x, a.y);
        ((__nv_bfloat162*)g_wfcb)[i * 2 + 1] = __floats2bfloat162_rn(a.z, a.w);
        float4 b = ((const float4*)wpr)[i];
        ((__nv_bfloat162*)g_wprb)[i * 2]     = __floats2bfloat162_rn(b.x, b.y);
        ((__nv_bfloat162*)g_wprb)[i * 2 + 1] = __floats2bfloat162_rn(b.z, b.w);
        return;
    }
    int r0 = (blockIdx.x - 256) * 4;
    #pragma unroll
    for (int i = 0; i < 4; i++) sCX[i][tid] = cx[(r0 + i) * DD + tid];
    __syncthreads();
    float acc[4];
    #pragma unroll
    for (int i = 0; i < 4; i++) acc[i] = bkv[DD + tid];
    for (int c = 0; c < DD; c++) {
        float w = wkv[c * 512 + DD + tid];
        #pragma unroll
        for (int i = 0; i < 4; i++) acc[i] += sCX[i][c] * w;
    }
    #pragma unroll
    for (int i = 0; i < 4; i++) sV[i][tid] = acc[i];
    __syncthreads();
    float a2[4];
    #pragma unroll
    for (int i = 0; i < 4; i++) a2[i] = bo[tid];
    for (int k = 0; k < DD; k++) {
        float w = wo[k * DD + tid];
        #pragma unroll
        for (int i = 0; i < 4; i++) a2[i] += sV[i][k] * w;
    }
    #pragma unroll
    for (int i = 0; i < 4; i++) g_yo[(r0 + i) * DD + tid] = a2[i];
}

// ---------------------------------------------------------------------------
// LN: x3 = LN2(LN1(x)+yo) -> out (fp32 residual base) and g_xb (bf16 GEMM A)
// ---------------------------------------------------------------------------
__global__ void __launch_bounds__(256)
ln_kernel(const float* __restrict__ x,
          const float* __restrict__ ln1w, const float* __restrict__ ln1b,
          const float* __restrict__ ln2w, const float* __restrict__ ln2b,
          float* __restrict__ out) {
    int warp = threadIdx.x >> 5;
    int lane = threadIdx.x & 31;
    size_t row = (size_t)blockIdx.x * 8 + warp;

    float lw1[8], lb1[8], lw2[8], lb2[8], yo[8];
    {
        float4 a, b;
        a = ((const float4*)ln1w)[lane*2]; b = ((const float4*)ln1w)[lane*2+1];
        lw1[0]=a.x;lw1[1]=a.y;lw1[2]=a.z;lw1[3]=a.w;lw1[4]=b.x;lw1[5]=b.y;lw1[6]=b.z;lw1[7]=b.w;
        a = ((const float4*)ln1b)[lane*2]; b = ((const float4*)ln1b)[lane*2+1];
        lb1[0]=a.x;lb1[1]=a.y;lb1[2]=a.z;lb1[3]=a.w;lb1[4]=b.x;lb1[5]=b.y;lb1[6]=b.z;lb1[7]=b.w;
        a = ((const float4*)ln2w)[lane*2]; b = ((const float4*)ln2w)[lane*2+1];
        lw2[0]=a.x;lw2[1]=a.y;lw2[2]=a.z;lw2[3]=a.w;lw2[4]=b.x;lw2[5]=b.y;lw2[6]=b.z;lw2[7]=b.w;
        a = ((const float4*)ln2b)[lane*2]; b = ((const float4*)ln2b)[lane*2+1];
        lb2[0]=a.x;lb2[1]=a.y;lb2[2]=a.z;lb2[3]=a.w;lb2[4]=b.x;lb2[5]=b.y;lb2[6]=b.z;lb2[7]=b.w;
        const float* yor = g_yo + (row >> 7) * DD;
        a = ((const float4*)yor)[lane*2]; b = ((const float4*)yor)[lane*2+1];
        yo[0]=a.x;yo[1]=a.y;yo[2]=a.z;yo[3]=a.w;yo[4]=b.x;yo[5]=b.y;yo[6]=b.z;yo[7]=b.w;
    }
    const float4* xr = (const float4*)(x + row * DD);
    float v[8];
    { float4 u0 = xr[lane*2], u1 = xr[lane*2+1];
      v[0]=u0.x;v[1]=u0.y;v[2]=u0.z;v[3]=u0.w;v[4]=u1.x;v[5]=u1.y;v[6]=u1.z;v[7]=u1.w; }
    float s = 0.f, q = 0.f;
    #pragma unroll
    for (int j = 0; j < 8; j++) { s += v[j]; q += v[j]*v[j]; }
    #pragma unroll
    for (int o = 16; o > 0; o >>= 1) { s += __shfl_xor_sync(~0u,s,o); q += __shfl_xor_sync(~0u,q,o); }
    float mu = s * (1.f/DD);
    float rs = rsqrtf(q * (1.f/DD) - mu*mu + 1e-5f);
    float tv[8]; s = 0.f; q = 0.f;
    #pragma unroll
    for (int j = 0; j < 8; j++) {
        tv[j] = (v[j]-mu)*rs*lw1[j] + lb1[j] + yo[j];
        s += tv[j]; q += tv[j]*tv[j];
    }
    #pragma unroll
    for (int o = 16; o > 0; o >>= 1) { s += __shfl_xor_sync(~0u,s,o); q += __shfl_xor_sync(~0u,q,o); }
    float mu2 = s * (1.f/DD);
    float rs2 = rsqrtf(q * (1.f/DD) - mu2*mu2 + 1e-5f);
    #pragma unroll
    for (int j = 0; j < 8; j++) v[j] = (tv[j]-mu2)*rs2*lw2[j] + lb2[j];

    float* orow = out + row * DD;
    ((float4*)orow)[lane*2]   = make_float4(v[0],v[1],v[2],v[3]);
    ((float4*)orow)[lane*2+1] = make_float4(v[4],v[5],v[6],v[7]);

    __nv_bfloat162 p0 = __floats2bfloat162_rn(v[0],v[1]);
    __nv_bfloat162 p1 = __floats2bfloat162_rn(v[2],v[3]);
    __nv_bfloat162 p2 = __floats2bfloat162_rn(v[4],v[5]);
    __nv_bfloat162 p3 = __floats2bfloat162_rn(v[6],v[7]);
    uint4 pk;
    pk.x = *(unsigned*)&p0; pk.y = *(unsigned*)&p1; pk.z = *(unsigned*)&p2; pk.w = *(unsigned*)&p3;
    *(uint4*)(g_xb + row * DD + lane * 8) = pk;
}

// ---------------------------------------------------------------------------
// GEMM core helpers: 128x128 tile, K-chunk 64, 3-stage cp.async pipeline.
// 8 warps: wm = warp&3 (32-row strip), wn = warp>>2 (64-col half).
// ---------------------------------------------------------------------------
#define GEMM_COMPUTE(sm, st)                                                      \
    {                                                                             \
        const __nv_bfloat16* Ab = (const __nv_bfloat16*)((sm) + (st) * ST_BYTES) + (wm * 32) * LDA; \
        const __nv_bfloat16* Bb = (const __nv_bfloat16*)((sm) + (st) * ST_BYTES + ST_A) + wn * 64;  \
        _Pragma("unroll")                                                         \
        for (int ks = 0; ks < 64; ks += 16) {                                     \
            wmma::fragment<wmma::matrix_a, 16, 16, 16, __nv_bfloat16, wmma::row_major> a0, a1; \
            wmma::load_matrix_sync(a0, Ab + ks, LDA);                             \
            wmma::load_matrix_sync(a1, Ab + 16 * LDA + ks, LDA);                  \
            _Pragma("unroll")                                                     \
            for (int n = 0; n < 4; n++) {                                         \
                wmma::fragment<wmma::matrix_b, 16, 16, 16, __nv_bfloat16, wmma::row_major> b; \
                wmma::load_matrix_sync(b, Bb + ks * LDB + n * 16, LDB);           \
                wmma::mma_sync(c0[n], a0, b, c0[n]);                              \
                wmma::mma_sync(c1[n], a1, b, c1[n]);                              \
            }                                                                     \
        }                                                                         \
    }

// stage fill: A[128x64] from (abase + r*astr + kt*64), B[64x128] from (bbase + (kt*64+r)*bstr + col0)
#define GEMM_FILL(sm, st, kt, abase, astr, bbase, bstr)                           \
    {                                                                             \
        char* A = (sm) + (st) * ST_BYTES;                                         \
        char* B = A + ST_A;                                                       \
        _Pragma("unroll")                                                         \
        for (int t = 0; t < 4; t++) {                                             \
            int idx = tid + t * 256, r = idx >> 3, qq = idx & 7;                  \
            cp16(A + (r * LDA + qq * 8) * 2, (abase) + (size_t)(row0 + r) * (astr) + (kt) * 64 + qq * 8); \
        }                                                                         \
        _Pragma("unroll")                                                         \
        for (int t = 0; t < 4; t++) {                                             \
            int idx = tid + t * 256, r = idx >> 4, qq = idx & 15;                 \
            cp16(B + (r * LDB + qq * 8) * 2, (bbase) + (size_t)((kt) * 64 + r) * (bstr) + col0 + qq * 8); \
        }                                                                         \
    }

// ---------------------------------------------------------------------------
// GEMM1: g_hb = gelu(g_xb @ Wfc + bfc)   [131072,256] x [256,1024], NCH=4
// ---------------------------------------------------------------------------
__global__ void __launch_bounds__(256, 2)
gemm1_kernel(const float* __restrict__ bfc) {
    extern __shared__ __align__(16) char sm[];
    int tid  = threadIdx.x;
    int warp = tid >> 5;
    int wm = warp & 3, wn = warp >> 2;
    size_t row0 = (size_t)(blockIdx.x >> 3) * 128;
    int col0 = (blockIdx.x & 7) * 128;

    wmma::fragment<wmma::accumulator, 16, 16, 16, float> c0[4], c1[4];
    #pragma unroll
    for (int n = 0; n < 4; n++) { wmma::fill_fragment(c0[n], 0.f); wmma::fill_fragment(c1[n], 0.f); }

    GEMM_FILL(sm, 0, 0, g_xb, 256, g_wfcb, 1024); CP_COMMIT();
    GEMM_FILL(sm, 1, 1, g_xb, 256, g_wfcb, 1024); CP_COMMIT();

    #pragma unroll
    for (int kt = 0; kt < 4; kt++) {
        CP_WAIT1();
        __syncthreads();
        if (kt + 2 < 4) { GEMM_FILL(sm, (kt + 2) % 3, kt + 2, g_xb, 256, g_wfcb, 1024); }
        CP_COMMIT();
        GEMM_COMPUTE(sm, kt % 3);
    }

    // epilogue: bias + gelu -> bf16 g_hb (single-pass staging)
    CP_WAIT0();
    __syncthreads();
    float* S = (float*)sm;
    float* Sp = S + (wm * 32) * LDS + wn * 64;
    #pragma unroll
    for (int n = 0; n < 4; n++) {
        wmma::store_matrix_sync(Sp + n * 16,            c0[n], LDS, wmma::mem_row_major);
        wmma::store_matrix_sync(Sp + 16 * LDS + n * 16, c1[n], LDS, wmma::mem_row_major);
    }
    __syncthreads();
    #pragma unroll
    for (int j = 0; j < 8; j++) {
        int cc = tid + j * 256, r = cc >> 4, q = cc & 15;
        const float* Sr = S + r * LDS + q * 8;
        float4 f0 = *(const float4*)(Sr);
        float4 f1 = *(const float4*)(Sr + 4);
        const float* bf = bfc + col0 + q * 8;
        f0.x = gelu_exact(f0.x + bf[0]); f0.y = gelu_exact(f0.y + bf[1]);
        f0.z = gelu_exact(f0.z + bf[2]); f0.w = gelu_exact(f0.w + bf[3]);
        f1.x = gelu_exact(f1.x + bf[4]); f1.y = gelu_exact(f1.y + bf[5]);
        f1.z = gelu_exact(f1.z + bf[6]); f1.w = gelu_exact(f1.w + bf[7]);
        __nv_bfloat162 q0 = __floats2bfloat162_rn(f0.x, f0.y);
        __nv_bfloat162 q1 = __floats2bfloat162_rn(f0.z, f0.w);
        __nv_bfloat162 q2 = __floats2bfloat162_rn(f1.x, f1.y);
        __nv_bfloat162 q3 = __floats2bfloat162_rn(f1.z, f1.w);
        uint4 pk;
        pk.x = *(unsigned*)&q0; pk.y = *(unsigned*)&q1;
        pk.z = *(unsigned*)&q2; pk.w = *(unsigned*)&q3;
        *(uint4*)(g_hb + (row0 + r) * 1024 + col0 + q * 8) = pk;
    }
}

// ---------------------------------------------------------------------------
// GEMM2: out = x3(out) + g_hb @ Wpr + bpr   [131072,1024] x [1024,256], NCH=16
// ---------------------------------------------------------------------------
__global__ void __launch_bounds__(256, 2)
gemm2_kernel(const float* __restrict__ bpr, float* __restrict__ out) {
    extern __shared__ __align__(16) char sm[];
    int tid  = threadIdx.x;
    int warp = tid >> 5;
    int wm = warp & 3, wn = warp >> 2;
    size_t row0 = (size_t)(blockIdx.x >> 1) * 128;
    int col0 = (blockIdx.x & 1) * 128;

    wmma::fragment<wmma::accumulator, 16, 16, 16, float> c0[4], c1[4];
    #pragma unroll
    for (int n = 0; n < 4; n++) { wmma::fill_fragment(c0[n], 0.f); wmma::fill_fragment(c1[n], 0.f); }

    GEMM_FILL(sm, 0, 0, g_hb, 1024, g_wprb, 256); CP_COMMIT();
    GEMM_FILL(sm, 1, 1, g_hb, 1024, g_wprb, 256); CP_COMMIT();

    for (int kt = 0; kt < 16; kt++) {
        CP_WAIT1();
        __syncthreads();
        if (kt + 2 < 16) { GEMM_FILL(sm, (kt + 2) % 3, kt + 2, g_hb, 1024, g_wprb, 256); }
        CP_COMMIT();
        GEMM_COMPUTE(sm, kt % 3);
    }

    // epilogue: out = x3(out) + acc + bpr (single-pass staging)
    CP_WAIT0();
    __syncthreads();
    float* S = (float*)sm;
    float* Sp = S + (wm * 32) * LDS + wn * 64;
    #pragma unroll
    for (int n = 0; n < 4; n++) {
        wmma::store_matrix_sync(Sp + n * 16,            c0[n], LDS, wmma::mem_row_major);
        wmma::store_matrix_sync(Sp + 16 * LDS + n * 16, c1[n], LDS, wmma::mem_row_major);
    }
    __syncthreads();
    #pragma unroll
    for (int j = 0; j < 8; j++) {
        int cc = tid + j * 256, r = cc >> 4, q = cc & 15;
        const float* Sr = S + r * LDS + q * 8;
        float* og = out + (row0 + r) * DD + col0 + q * 8;
        const float* bp = bpr + col0 + q * 8;
        float4 f0 = *(const float4*)(Sr);
        float4 f1 = *(const float4*)(Sr + 4);
        float4 x0 = *(const float4*)(og);
        float4 x1 = *(const float4*)(og + 4);
        f0.x += x0.x + bp[0]; f0.y += x0.y + bp[1]; f0.z += x0.z + bp[2]; f0.w += x0.w + bp[3];
        f1.x += x1.x + bp[4]; f1.y += x1.y + bp[5]; f1.z += x1.z + bp[6]; f1.w += x1.w + bp[7];
        *(float4*)(og)     = f0;
        *(float4*)(og + 4) = f1;
    }
}

// ---------------------------------------------------------------------------
extern "C" void kernel_launch(void* const* d_in, const int* in_sizes, int n_in,
                              void* d_out, int out_size) {
    const float* x    = (const float*)d_in[0];
    const float* cx   = (const float*)d_in[1];
    const float* ln1w = (const float*)d_in[2];
    const float* ln1b = (const float*)d_in[3];
    // d_in[4]=wq, d_in[5]=bq: unused (uniform softmax over equal logits; V constant over keys)
    const float* wkv  = (const float*)d_in[6];
    const float* bkv  = (const float*)d_in[7];
    const float* wo   = (const float*)d_in[8];
    const float* bo   = (const float*)d_in[9];
    const float* ln2w = (const float*)d_in[10];
    const float* ln2b = (const float*)d_in[11];
    const float* wfc  = (const float*)d_in[12];
    const float* bfc  = (const float*)d_in[13];
    const float* wpr  = (const float*)d_in[14];
    const float* bpr  = (const float*)d_in[15];
    float* out = (float*)d_out;

    cudaFuncSetAttribute(gemm1_kernel, cudaFuncAttributeMaxDynamicSharedMemorySize, SMEM_PIPE);
    cudaFuncSetAttribute(gemm2_kernel, cudaFuncAttributeMaxDynamicSharedMemorySize, SMEM_PIPE);

    prep_kernel<<<512, 256>>>(wfc, wpr, cx, wkv, bkv, wo, bo);
    ln_kernel<<<16384, 256>>>(x, ln1w, ln1b, ln2w, ln2b, out);
    gemm1_kernel<<<8192, 256, SMEM_PIPE>>>(bfc);
    gemm2_kernel<<<2048, 256, SMEM_PIPE>>>(bpr, out);
}

// round 12
// speedup vs baseline: 1.3548x; 1.0081x over previous
#include <cstdint>
#include <cuda_runtime.h>
#include <cuda_bf16.h>
#include <mma.h>
#include <math.h>

using namespace nvcuda;

#define DD 256

#define LDA 72     // A stage stride (bf16): 64 + 8 pad
#define LDB 136    // B stage stride (bf16): 128 + 8 pad
#define LDS 132    // epilogue staging stride (f32)

// 2-stage pipeline arena: stage = A[64x64] + B[64x128] (bf16, padded)
#define ST_A     9216             // 64*72*2
#define ST_BYTES 26624            // + 64*136*2
#define SMEM_PIPE (2 * ST_BYTES)  // 53248; epilogue staging 64*132*4 = 33792 fits

__device__ __nv_bfloat16 g_wfcb[256 * 1024];     // [k=256,  n=1024]
__device__ __nv_bfloat16 g_wprb[1024 * 256];     // [k=1024, n=256]
__device__ float         g_yo[1024 * DD];
__device__ __nv_bfloat16 g_xb[131072 * 256];           // x3 bf16
__device__ __nv_bfloat16 g_hb[(size_t)131072 * 1024];  // gelu(h) bf16

// ---------------------------------------------------------------------------
__device__ __forceinline__ void cp16(void* sdst, const void* gsrc) {
    unsigned s = (unsigned)__cvta_generic_to_shared(sdst);
    asm volatile("cp.async.cg.shared.global [%0], [%1], 16;" :: "r"(s), "l"(gsrc));
}
#define CP_COMMIT() asm volatile("cp.async.commit_group;" ::: "memory")
#define CP_WAIT1()  asm volatile("cp.async.wait_group 1;" ::: "memory")
#define CP_WAIT0()  asm volatile("cp.async.wait_group 0;" ::: "memory")

__device__ __forceinline__ float gelu_exact(float v) {
    return 0.5f * v * (1.f + erff(v * 0.70710678118654752f));
}

// ---------------------------------------------------------------------------
// prep: blocks 0-255 convert weights fp32->bf16; blocks 256-511 compute yo.
// yo[b,a,:] = ((cx @ wkv)[:, D:2D] + bkv[D:2D]) @ wo + bo
// ---------------------------------------------------------------------------
__global__ void prep_kernel(const float* __restrict__ wfc, const float* __restrict__ wpr,
                            const float* __restrict__ cx,  const float* __restrict__ wkv,
                            const float* __restrict__ bkv, const float* __restrict__ wo,
                            const float* __restrict__ bo) {
    __shared__ float sCX[4][DD];
    __shared__ float sV[4][DD];
    int tid = threadIdx.x;
    if (blockIdx.x < 256) {
        int i = blockIdx.x * 256 + tid;
        float4 a = ((const float4*)wfc)[i];
        ((__nv_bfloat162*)g_wfcb)[i * 2]     = __floats2bfloat162_rn(a.x, a.y);
        ((__nv_bfloat162*)g_wfcb)[i * 2 + 1] = __floats2bfloat162_rn(a.z, a.w);
        float4 b = ((const float4*)wpr)[i];
        ((__nv_bfloat162*)g_wprb)[i * 2]     = __floats2bfloat162_rn(b.x, b.y);
        ((__nv_bfloat162*)g_wprb)[i * 2 + 1] = __floats2bfloat162_rn(b.z, b.w);
        return;
    }
    int r0 = (blockIdx.x - 256) * 4;
    #pragma unroll
    for (int i = 0; i < 4; i++) sCX[i][tid] = cx[(r0 + i) * DD + tid];
    __syncthreads();
    float acc[4];
    #pragma unroll
    for (int i = 0; i < 4; i++) acc[i] = bkv[DD + tid];
    for (int c = 0; c < DD; c++) {
        float w = wkv[c * 512 + DD + tid];
        #pragma unroll
        for (int i = 0; i < 4; i++) acc[i] += sCX[i][c] * w;
    }
    #pragma unroll
    for (int i = 0; i < 4; i++) sV[i][tid] = acc[i];
    __syncthreads();
    float a2[4];
    #pragma unroll
    for (int i = 0; i < 4; i++) a2[i] = bo[tid];
    for (int k = 0; k < DD; k++) {
        float w = wo[k * DD + tid];
        #pragma unroll
        for (int i = 0; i < 4; i++) a2[i] += sV[i][k] * w;
    }
    #pragma unroll
    for (int i = 0; i < 4; i++) g_yo[(r0 + i) * DD + tid] = a2[i];
}

// ---------------------------------------------------------------------------
// LN: x3 = LN2(LN1(x)+yo) -> out (fp32 residual base) and g_xb (bf16 GEMM A)
// ---------------------------------------------------------------------------
__global__ void __launch_bounds__(256)
ln_kernel(const float* __restrict__ x,
          const float* __restrict__ ln1w, const float* __restrict__ ln1b,
          const float* __restrict__ ln2w, const float* __restrict__ ln2b,
          float* __restrict__ out) {
    int warp = threadIdx.x >> 5;
    int lane = threadIdx.x & 31;
    size_t row = (size_t)blockIdx.x * 8 + warp;

    float lw1[8], lb1[8], lw2[8], lb2[8], yo[8];
    {
        float4 a, b;
        a = ((const float4*)ln1w)[lane*2]; b = ((const float4*)ln1w)[lane*2+1];
        lw1[0]=a.x;lw1[1]=a.y;lw1[2]=a.z;lw1[3]=a.w;lw1[4]=b.x;lw1[5]=b.y;lw1[6]=b.z;lw1[7]=b.w;
        a = ((const float4*)ln1b)[lane*2]; b = ((const float4*)ln1b)[lane*2+1];
        lb1[0]=a.x;lb1[1]=a.y;lb1[2]=a.z;lb1[3]=a.w;lb1[4]=b.x;lb1[5]=b.y;lb1[6]=b.z;lb1[7]=b.w;
        a = ((const float4*)ln2w)[lane*2]; b = ((const float4*)ln2w)[lane*2+1];
        lw2[0]=a.x;lw2[1]=a.y;lw2[2]=a.z;lw2[3]=a.w;lw2[4]=b.x;lw2[5]=b.y;lw2[6]=b.z;lw2[7]=b.w;
        a = ((const float4*)ln2b)[lane*2]; b = ((const float4*)ln2b)[lane*2+1];
        lb2[0]=a.x;lb2[1]=a.y;lb2[2]=a.z;lb2[3]=a.w;lb2[4]=b.x;lb2[5]=b.y;lb2[6]=b.z;lb2[7]=b.w;
        const float* yor = g_yo + (row >> 7) * DD;
        a = ((const float4*)yor)[lane*2]; b = ((const float4*)yor)[lane*2+1];
        yo[0]=a.x;yo[1]=a.y;yo[2]=a.z;yo[3]=a.w;yo[4]=b.x;yo[5]=b.y;yo[6]=b.z;yo[7]=b.w;
    }
    const float4* xr = (const float4*)(x + row * DD);
    float v[8];
    { float4 u0 = xr[lane*2], u1 = xr[lane*2+1];
      v[0]=u0.x;v[1]=u0.y;v[2]=u0.z;v[3]=u0.w;v[4]=u1.x;v[5]=u1.y;v[6]=u1.z;v[7]=u1.w; }
    float s = 0.f, q = 0.f;
    #pragma unroll
    for (int j = 0; j < 8; j++) { s += v[j]; q += v[j]*v[j]; }
    #pragma unroll
    for (int o = 16; o > 0; o >>= 1) { s += __shfl_xor_sync(~0u,s,o); q += __shfl_xor_sync(~0u,q,o); }
    float mu = s * (1.f/DD);
    float rs = rsqrtf(q * (1.f/DD) - mu*mu + 1e-5f);
    float tv[8]; s = 0.f; q = 0.f;
    #pragma unroll
    for (int j = 0; j < 8; j++) {
        tv[j] = (v[j]-mu)*rs*lw1[j] + lb1[j] + yo[j];
        s += tv[j]; q += tv[j]*tv[j];
    }
    #pragma unroll
    for (int o = 16; o > 0; o >>= 1) { s += __shfl_xor_sync(~0u,s,o); q += __shfl_xor_sync(~0u,q,o); }
    float mu2 = s * (1.f/DD);
    float rs2 = rsqrtf(q * (1.f/DD) - mu2*mu2 + 1e-5f);
    #pragma unroll
    for (int j = 0; j < 8; j++) v[j] = (tv[j]-mu2)*rs2*lw2[j] + lb2[j];

    float* orow = out + row * DD;
    ((float4*)orow)[lane*2]   = make_float4(v[0],v[1],v[2],v[3]);
    ((float4*)orow)[lane*2+1] = make_float4(v[4],v[5],v[6],v[7]);

    __nv_bfloat162 p0 = __floats2bfloat162_rn(v[0],v[1]);
    __nv_bfloat162 p1 = __floats2bfloat162_rn(v[2],v[3]);
    __nv_bfloat162 p2 = __floats2bfloat162_rn(v[4],v[5]);
    __nv_bfloat162 p3 = __floats2bfloat162_rn(v[6],v[7]);
    uint4 pk;
    pk.x = *(unsigned*)&p0; pk.y = *(unsigned*)&p1; pk.z = *(unsigned*)&p2; pk.w = *(unsigned*)&p3;
    *(uint4*)(g_xb + row * DD + lane * 8) = pk;
}

// ---------------------------------------------------------------------------
// GEMM core: 64x128 CTA tile, 128 threads (4 warps), K-chunk 64, 2 stages.
// Warp tile 32x64: wm = warp&1 (32-row strip), wn = warp>>1 (64-col half).
// ---------------------------------------------------------------------------
#define GEMM_COMPUTE(sm, st)                                                      \
    {                                                                             \
        const __nv_bfloat16* Ab = (const __nv_bfloat16*)((sm) + (st) * ST_BYTES) + (wm * 32) * LDA; \
        const __nv_bfloat16* Bb = (const __nv_bfloat16*)((sm) + (st) * ST_BYTES + ST_A) + wn * 64;  \
        _Pragma("unroll")                                                         \
        for (int ks = 0; ks < 64; ks += 16) {                                     \
            wmma::fragment<wmma::matrix_a, 16, 16, 16, __nv_bfloat16, wmma::row_major> a0, a1; \
            wmma::load_matrix_sync(a0, Ab + ks, LDA);                             \
            wmma::load_matrix_sync(a1, Ab + 16 * LDA + ks, LDA);                  \
            _Pragma("unroll")                                                     \
            for (int n = 0; n < 4; n++) {                                         \
                wmma::fragment<wmma::matrix_b, 16, 16, 16, __nv_bfloat16, wmma::row_major> b; \
                wmma::load_matrix_sync(b, Bb + ks * LDB + n * 16, LDB);           \
                wmma::mma_sync(c0[n], a0, b, c0[n]);                              \
                wmma::mma_sync(c1[n], a1, b, c1[n]);                              \
            }                                                                     \
        }                                                                         \
    }

// stage fill: A[64x64] from (abase + (row0+r)*astr + kt*64), B[64x128] from (bbase + (kt*64+r)*bstr + col0)
#define GEMM_FILL(sm, st, kt, abase, astr, bbase, bstr)                           \
    {                                                                             \
        char* A = (sm) + (st) * ST_BYTES;                                         \
        char* B = A + ST_A;                                                       \
        _Pragma("unroll")                                                         \
        for (int t = 0; t < 4; t++) {                                             \
            int idx = tid + t * 128, r = idx >> 3, qq = idx & 7;                  \
            cp16(A + (r * LDA + qq * 8) * 2, (abase) + (size_t)(row0 + r) * (astr) + (kt) * 64 + qq * 8); \
        }                                                                         \
        _Pragma("unroll")                                                         \
        for (int t = 0; t < 8; t++) {                                             \
            int idx = tid + t * 128, r = idx >> 4, qq = idx & 15;                 \
            cp16(B + (r * LDB + qq * 8) * 2, (bbase) + (size_t)((kt) * 64 + r) * (bstr) + col0 + qq * 8); \
        }                                                                         \
    }

// ---------------------------------------------------------------------------
// GEMM1: g_hb = gelu(g_xb @ Wfc + bfc)   [131072,256] x [256,1024], NCH=4
// ---------------------------------------------------------------------------
__global__ void __launch_bounds__(128, 4)
gemm1_kernel(const float* __restrict__ bfc) {
    extern __shared__ __align__(16) char sm[];
    int tid  = threadIdx.x;
    int warp = tid >> 5;
    int wm = warp & 1, wn = warp >> 1;
    size_t row0 = (size_t)(blockIdx.x >> 3) * 64;
    int col0 = (blockIdx.x & 7) * 128;

    wmma::fragment<wmma::accumulator, 16, 16, 16, float> c0[4], c1[4];
    #pragma unroll
    for (int n = 0; n < 4; n++) { wmma::fill_fragment(c0[n], 0.f); wmma::fill_fragment(c1[n], 0.f); }

    GEMM_FILL(sm, 0, 0, g_xb, 256, g_wfcb, 1024); CP_COMMIT();
    GEMM_FILL(sm, 1, 1, g_xb, 256, g_wfcb, 1024); CP_COMMIT();

    #pragma unroll
    for (int kt = 0; kt < 4; kt++) {
        CP_WAIT1();
        __syncthreads();
        GEMM_COMPUTE(sm, kt & 1);
        __syncthreads();
        if (kt + 2 < 4) { GEMM_FILL(sm, kt & 1, kt + 2, g_xb, 256, g_wfcb, 1024); }
        CP_COMMIT();
    }

    // epilogue: bias + gelu -> bf16 g_hb
    CP_WAIT0();
    __syncthreads();
    float* S = (float*)sm;
    float* Sp = S + (wm * 32) * LDS + wn * 64;
    #pragma unroll
    for (int n = 0; n < 4; n++) {
        wmma::store_matrix_sync(Sp + n * 16,            c0[n], LDS, wmma::mem_row_major);
        wmma::store_matrix_sync(Sp + 16 * LDS + n * 16, c1[n], LDS, wmma::mem_row_major);
    }
    __syncthreads();
    #pragma unroll
    for (int j = 0; j < 8; j++) {
        int cc = tid + j * 128, r = cc >> 4, q = cc & 15;
        const float* Sr = S + r * LDS + q * 8;
        float4 f0 = *(const float4*)(Sr);
        float4 f1 = *(const float4*)(Sr + 4);
        const float* bf = bfc + col0 + q * 8;
        f0.x = gelu_exact(f0.x + bf[0]); f0.y = gelu_exact(f0.y + bf[1]);
        f0.z = gelu_exact(f0.z + bf[2]); f0.w = gelu_exact(f0.w + bf[3]);
        f1.x = gelu_exact(f1.x + bf[4]); f1.y = gelu_exact(f1.y + bf[5]);
        f1.z = gelu_exact(f1.z + bf[6]); f1.w = gelu_exact(f1.w + bf[7]);
        __nv_bfloat162 q0 = __floats2bfloat162_rn(f0.x, f0.y);
        __nv_bfloat162 q1 = __floats2bfloat162_rn(f0.z, f0.w);
        __nv_bfloat162 q2 = __floats2bfloat162_rn(f1.x, f1.y);
        __nv_bfloat162 q3 = __floats2bfloat162_rn(f1.z, f1.w);
        uint4 pk;
        pk.x = *(unsigned*)&q0; pk.y = *(unsigned*)&q1;
        pk.z = *(unsigned*)&q2; pk.w = *(unsigned*)&q3;
        *(uint4*)(g_hb + (row0 + r) * 1024 + col0 + q * 8) = pk;
    }
}

// ---------------------------------------------------------------------------
// GEMM2: out = x3(out) + g_hb @ Wpr + bpr   [131072,1024] x [1024,256], NCH=16
// ---------------------------------------------------------------------------
__global__ void __launch_bounds__(128, 4)
gemm2_kernel(const float* __restrict__ bpr, float* __restrict__ out) {
    extern __shared__ __align__(16) char sm[];
    int tid  = threadIdx.x;
    int warp = tid >> 5;
    int wm = warp & 1, wn = warp >> 1;
    size_t row0 = (size_t)(blockIdx.x >> 1) * 64;
    int col0 = (blockIdx.x & 1) * 128;

    wmma::fragment<wmma::accumulator, 16, 16, 16, float> c0[4], c1[4];
    #pragma unroll
    for (int n = 0; n < 4; n++) { wmma::fill_fragment(c0[n], 0.f); wmma::fill_fragment(c1[n], 0.f); }

    GEMM_FILL(sm, 0, 0, g_hb, 1024, g_wprb, 256); CP_COMMIT();
    GEMM_FILL(sm, 1, 1, g_hb, 1024, g_wprb, 256); CP_COMMIT();

    for (int kt = 0; kt < 16; kt++) {
        CP_WAIT1();
        __syncthreads();
        GEMM_COMPUTE(sm, kt & 1);
        __syncthreads();
        if (kt + 2 < 16) { GEMM_FILL(sm, kt & 1, kt + 2, g_hb, 1024, g_wprb, 256); }
        CP_COMMIT();
    }

    // epilogue: out = x3(out) + acc + bpr
    CP_WAIT0();
    __syncthreads();
    float* S = (float*)sm;
    float* Sp = S + (wm * 32) * LDS + wn * 64;
    #pragma unroll
    for (int n = 0; n < 4; n++) {
        wmma::store_matrix_sync(Sp + n * 16,            c0[n], LDS, wmma::mem_row_major);
        wmma::store_matrix_sync(Sp + 16 * LDS + n * 16, c1[n], LDS, wmma::mem_row_major);
    }
    __syncthreads();
    #pragma unroll
    for (int j = 0; j < 8; j++) {
        int cc = tid + j * 128, r = cc >> 4, q = cc & 15;
        const float* Sr = S + r * LDS + q * 8;
        float* og = out + (row0 + r) * DD + col0 + q * 8;
        const float* bp = bpr + col0 + q * 8;
        float4 f0 = *(const float4*)(Sr);
        float4 f1 = *(const float4*)(Sr + 4);
        float4 x0 = *(const float4*)(og);
        float4 x1 = *(const float4*)(og + 4);
        f0.x += x0.x + bp[0]; f0.y += x0.y + bp[1]; f0.z += x0.z + bp[2]; f0.w += x0.w + bp[3];
        f1.x += x1.x + bp[4]; f1.y += x1.y + bp[5]; f1.z += x1.z + bp[6]; f1.w += x1.w + bp[7];
        *(float4*)(og)     = f0;
        *(float4*)(og + 4) = f1;
    }
}

// ---------------------------------------------------------------------------
extern "C" void kernel_launch(void* const* d_in, const int* in_sizes, int n_in,
                              void* d_out, int out_size) {
    const float* x    = (const float*)d_in[0];
    const float* cx   = (const float*)d_in[1];
    const float* ln1w = (const float*)d_in[2];
    const float* ln1b = (const float*)d_in[3];
    // d_in[4]=wq, d_in[5]=bq: unused (uniform softmax over equal logits; V constant over keys)
    const float* wkv  = (const float*)d_in[6];
    const float* bkv  = (const float*)d_in[7];
    const float* wo   = (const float*)d_in[8];
    const float* bo   = (const float*)d_in[9];
    const float* ln2w = (const float*)d_in[10];
    const float* ln2b = (const float*)d_in[11];
    const float* wfc  = (const float*)d_in[12];
    const float* bfc  = (const float*)d_in[13];
    const float* wpr  = (const float*)d_in[14];
    const float* bpr  = (const float*)d_in[15];
    float* out = (float*)d_out;

    cudaFuncSetAttribute(gemm1_kernel, cudaFuncAttributeMaxDynamicSharedMemorySize, SMEM_PIPE);
    cudaFuncSetAttribute(gemm2_kernel, cudaFuncAttributeMaxDynamicSharedMemorySize, SMEM_PIPE);

    prep_kernel<<<512, 256>>>(wfc, wpr, cx, wkv, bkv, wo, bo);
    ln_kernel<<<16384, 256>>>(x, ln1w, ln1b, ln2w, ln2b, out);
    gemm1_kernel<<<16384, 128, SMEM_PIPE>>>(bfc);
    gemm2_kernel<<<4096, 128, SMEM_PIPE>>>(bpr, out);
}